// round 6
// baseline (speedup 1.0000x reference)
#include <cuda_runtime.h>
#include <cstdint>

#define NN 100000
#define NH 20000
#define NE 800000
#define NKA (NH*2)     // hedge-type keys
#define NKB (NN*2)     // node-type keys
#define NBA ((NKA + 1023) / 1024)
#define NBB ((NKB + 1023) / 1024)

// ---------------- static device buffers ------------------------------------
__device__ __align__(16) float g_aggA[(size_t)2*NH*64];  // (Σx)/cnt per (t,h)
__device__ __align__(16) float g_efm[(size_t)2*NH*64];   // aggA @ Wcomb_t
__device__ int g_cntA[NKA], g_offA[NKA], g_curA[NKA];
__device__ int g_cntB[NKB], g_offB[NKB], g_curB[NKB];
__device__ int g_baseA, g_baseB;
__device__ int g_sortA[NE];   // node ids, sorted by (hedge,type)
__device__ int g_sortB[NE];   // efm row offsets (floats), sorted by (node,type)
// Pre-swizzled tf32 B-images
__device__ __align__(16) float g_Bef[2*2*64*32];   // Wcomb_t images
__device__ __align__(16) float g_Bgru[4*256*32];
__device__ float g_bias[256];
__device__ float g_bcmix[64];

// ---------------- helpers ---------------------------------------------------
__device__ __forceinline__ float to_tf32(float v) {
    uint32_t u; asm("cvt.rna.tf32.f32 %0, %1;" : "=r"(u) : "f"(v));
    return __uint_as_float(u);
}
__device__ __forceinline__ int swz(int kk, int row) {
    int r = kk & 7;
    int pos = (r < 4) ? (r * 2) : ((r - 4) * 2 + 1);
    int sc = (kk & 24) + pos;
    return (sc + ((row & 3) << 3)) & 31;
}
__device__ __forceinline__ void mma_tf32(float* c, const uint32_t* a,
                                         uint32_t b0, uint32_t b1) {
    asm volatile(
        "mma.sync.aligned.m16n8k8.row.col.f32.tf32.tf32.f32 "
        "{%0,%1,%2,%3}, {%4,%5,%6,%7}, {%8,%9}, {%0,%1,%2,%3};"
        : "+f"(c[0]), "+f"(c[1]), "+f"(c[2]), "+f"(c[3])
        : "r"(a[0]), "r"(a[1]), "r"(a[2]), "r"(a[3]), "r"(b0), "r"(b1));
}
__device__ __forceinline__ float sigf(float x) { return 1.f / (1.f + __expf(-x)); }
__device__ __forceinline__ float tanh_fast(float x) {
    return 1.f - 2.f / (__expf(2.f * x) + 1.f);
}

// ---------------- zero counters ---------------------------------------------
__global__ void k_zero_cnt() {
    int i = blockIdx.x * 256 + threadIdx.x;
    if (i < NKA) g_cntA[i] = 0;
    if (i < NKB) g_cntB[i] = 0;
    if (i == 0) { g_baseA = 0; g_baseB = 0; }
}

// ---------------- histogram -------------------------------------------------
__global__ void k_hist(const int* __restrict__ ni, const int* __restrict__ hi,
                       const int* __restrict__ ea) {
    int e = blockIdx.x * 256 + threadIdx.x;
    if (e >= NE) return;
    int t = ea[e];
    atomicAdd(&g_cntA[hi[e] * 2 + t], 1);
    atomicAdd(&g_cntB[ni[e] * 2 + t], 1);
}

// ---------------- parallel offsets: block scan + atomic range claim ---------
__global__ __launch_bounds__(1024) void k_offsets() {
    __shared__ int sm[1024];
    __shared__ int blockBase;
    int b = blockIdx.x;
    const int* cnt; int* off; int* cur; int n; int* gbase;
    if (b < NBA) { cnt = g_cntA; off = g_offA; cur = g_curA; n = NKA; gbase = &g_baseA; }
    else { b -= NBA; cnt = g_cntB; off = g_offB; cur = g_curB; n = NKB; gbase = &g_baseB; }
    int tid = threadIdx.x;
    int i = b * 1024 + tid;
    int v = (i < n) ? cnt[i] : 0;
    sm[tid] = v;
    __syncthreads();
    for (int d = 1; d < 1024; d <<= 1) {
        int t = (tid >= d) ? sm[tid - d] : 0;
        __syncthreads();
        sm[tid] += t;
        __syncthreads();
    }
    if (tid == 1023) blockBase = atomicAdd(gbase, sm[1023]);
    __syncthreads();
    if (i < n) {
        int o = blockBase + sm[tid] - v;
        off[i] = o; cur[i] = o;
    }
}

// ---------------- permute: build both sorted lists --------------------------
__global__ void k_perm(const int* __restrict__ ni, const int* __restrict__ hi,
                       const int* __restrict__ ea) {
    int e = blockIdx.x * 256 + threadIdx.x;
    if (e >= NE) return;
    int n = ni[e], h = hi[e], t = ea[e];
    int pA = atomicAdd(&g_curA[h * 2 + t], 1);
    g_sortA[pA] = n;
    int pB = atomicAdd(&g_curB[n * 2 + t], 1);
    g_sortB[pB] = (t * NH + h) * 64;
}

// ---------------- prep: swizzled tf32 B-images + biases ---------------------
__global__ void k_prep(const float* __restrict__ Wc, const float* __restrict__ Wmix,
                       const float* __restrict__ bmix, const float* __restrict__ bconv,
                       const float* __restrict__ Wih, const float* __restrict__ Whh,
                       const float* __restrict__ bih, const float* __restrict__ bhh) {
    int idx = blockIdx.x * blockDim.x + threadIdx.x;
    if (idx < 8192) {                     // Bef: [2][2 kc][64 c][32]
        int t = idx >> 12, rem = idx & 4095;
        int kc = rem >> 11, rem2 = rem & 2047, c = rem2 >> 5, kk = rem2 & 31;
        int k = kc * 32 + kk;
        float s = 0.f;
        const float* wr = Wc + t * 4096 + k * 64;
        const float* wm = Wmix + (size_t)t * 64 * 64 + c;
#pragma unroll 8
        for (int m = 0; m < 64; m++) s += wr[m] * wm[(size_t)m * 64];
        g_Bef[((t * 2 + kc) * 64 + c) * 32 + swz(kk, c)] = to_tf32(s);
    } else if (idx < 40960) {             // Bgru: [4][256][32], c = j*4+seg
        int i = idx - 8192;
        int kc = i >> 13, rem = i & 8191, c = rem >> 5, kk = rem & 31;
        int k = kc * 32 + kk;
        int j = c >> 2, seg = c & 3;
        float v = 0.f;
        if (k < 64) {
            if (seg == 0)      v = Wih[k * 192 + j];
            else if (seg == 1) v = Wih[k * 192 + 64 + j];
            else if (seg == 2) v = Wih[k * 192 + 128 + j];
        } else {
            int k2 = k - 64;
            if (seg == 0)      v = Whh[k2 * 192 + j];
            else if (seg == 1) v = Whh[k2 * 192 + 64 + j];
            else if (seg == 3) v = Whh[k2 * 192 + 128 + j];
        }
        g_Bgru[(kc * 256 + c) * 32 + swz(kk, c)] = to_tf32(v);
    } else if (idx < 40960 + 256) {       // GRU bias (seg-major)
        int c = idx - 40960;
        int seg = c >> 6, j = c & 63;
        float b;
        if (seg == 0)      b = bih[j] + bhh[j];
        else if (seg == 1) b = bih[64 + j] + bhh[64 + j];
        else if (seg == 2) b = bih[128 + j];
        else               b = bhh[128 + j];
        g_bias[c] = b;
    } else if (idx < 40960 + 256 + 64) {  // folded mix bias
        int j = idx - 40960 - 256;
        float s = bmix[j];
        for (int k = 0; k < 128; k++) s += bconv[k] * Wmix[k * 64 + j];
        g_bcmix[j] = s;
    }
}

// ---------------- gather A: aggA[t,h] = (1/cnt) * sum x[node] ----------------
__global__ __launch_bounds__(256) void k_gatherA(const float* __restrict__ x) {
    int key = (blockIdx.x * 256 + threadIdx.x) >> 5;
    if (key >= NKA) return;
    int lane = threadIdx.x & 31;
    int t = key & 1, h = key >> 1;
    int base = g_offA[key], cnt = g_cntA[key];
    const float* xb = x + lane * 2;
    float ax = 0.f, ay = 0.f;
    int i = 0;
    for (; i + 4 <= cnt; i += 4) {
        int n0 = g_sortA[base + i + 0];
        int n1 = g_sortA[base + i + 1];
        int n2 = g_sortA[base + i + 2];
        int n3 = g_sortA[base + i + 3];
        float2 v0 = *(const float2*)(xb + (size_t)n0 * 64);
        float2 v1 = *(const float2*)(xb + (size_t)n1 * 64);
        float2 v2 = *(const float2*)(xb + (size_t)n2 * 64);
        float2 v3 = *(const float2*)(xb + (size_t)n3 * 64);
        ax += (v0.x + v1.x) + (v2.x + v3.x);
        ay += (v0.y + v1.y) + (v2.y + v3.y);
    }
    for (; i < cnt; i++) {
        int n = g_sortA[base + i];
        float2 v = *(const float2*)(xb + (size_t)n * 64);
        ax += v.x; ay += v.y;
    }
    float s = (cnt > 0) ? 1.f / (float)cnt : 0.f;
    *(float2*)&g_aggA[((size_t)t * NH + h) * 64 + lane * 2] = make_float2(ax * s, ay * s);
}

// ---------------- GEMM: efm = aggA @ Wcomb_t   (M=NH per type, N=64, K=64) --
__global__ __launch_bounds__(256) void k_mma_ef() {
    __shared__ __align__(16) float As[128][32];
    __shared__ __align__(16) float Bs[64][32];
    int tid = threadIdx.x;
    int lane = tid & 31, warp = tid >> 5;
    int warpM = warp >> 1, warpN = warp & 1;
    int g = lane >> 2, t4 = lane & 3;
    int rot = (g & 3) << 3;
    int n0 = blockIdx.x * 128;
    int ty = blockIdx.y;
    float acc[2][4][4] = {};
    for (int kc = 0; kc < 2; kc++) {
        __syncthreads();
        for (int i = tid; i < 4096; i += 256) {
            int m = i >> 5, kk = i & 31;
            int n = n0 + m;
            float v = (n < NH) ? g_aggA[((size_t)ty * NH + n) * 64 + kc * 32 + kk] : 0.f;
            As[m][swz(kk, m)] = to_tf32(v);
        }
        const float4* src = (const float4*)&g_Bef[(ty * 2 + kc) * 2048];
        float4* dst = (float4*)&Bs[0][0];
        for (int i = tid; i < 512; i += 256) dst[i] = src[i];
        __syncthreads();
#pragma unroll
        for (int s = 0; s < 4; s++) {
            int pc = (s * 8 + 2 * t4 + rot) & 31;
            uint32_t a[2][4];
#pragma unroll
            for (int mt = 0; mt < 2; mt++) {
                int r = warpM * 32 + mt * 16 + g;
                float2 lo = *(const float2*)&As[r][pc];
                float2 hi = *(const float2*)&As[r + 8][pc];
                a[mt][0] = __float_as_uint(lo.x); a[mt][1] = __float_as_uint(hi.x);
                a[mt][2] = __float_as_uint(lo.y); a[mt][3] = __float_as_uint(hi.y);
            }
#pragma unroll
            for (int nt = 0; nt < 4; nt++) {
                int c = warpN * 32 + nt * 8 + g;
                float2 b = *(const float2*)&Bs[c][pc];
                uint32_t b0 = __float_as_uint(b.x), b1 = __float_as_uint(b.y);
                mma_tf32(acc[0][nt], a[0], b0, b1);
                mma_tf32(acc[1][nt], a[1], b0, b1);
            }
        }
    }
#pragma unroll
    for (int mt = 0; mt < 2; mt++) {
        int r = n0 + warpM * 32 + mt * 16 + g;
#pragma unroll
        for (int nt = 0; nt < 4; nt++) {
            int c = warpN * 32 + nt * 8 + 2 * t4;
            if (r < NH)
                *(float2*)&g_efm[((size_t)ty * NH + r) * 64 + c] =
                    make_float2(acc[mt][nt][0], acc[mt][nt][1]);
            if (r + 8 < NH)
                *(float2*)&g_efm[((size_t)ty * NH + r + 8) * 64 + c] =
                    make_float2(acc[mt][nt][2], acc[mt][nt][3]);
        }
    }
}

// ---------------- fused: gatherB + GRU GEMM + gates + readout ---------------
// dyn smem: Hs[128][64] | As[128][32] | Bs[256][32] | Wro3[64][4] | sred[128][4]
#define GRU_SMEM (32768 + 16384 + 32768 + 1024 + 2048)
__global__ __launch_bounds__(512) void k_gru_fused(const float* __restrict__ h_prev,
                                                   const float* __restrict__ Wro,
                                                   const float* __restrict__ bro,
                                                   float* __restrict__ out_h,
                                                   float* __restrict__ out3) {
    extern __shared__ __align__(16) char smem_raw[];
    float (*Hs)[64]  = reinterpret_cast<float(*)[64]>(smem_raw);
    float (*As)[32]  = reinterpret_cast<float(*)[32]>(smem_raw + 32768);
    float (*Bs)[32]  = reinterpret_cast<float(*)[32]>(smem_raw + 49152);
    float (*Wro3)[4] = reinterpret_cast<float(*)[4]>(smem_raw + 81920);
    float (*sred)[4] = reinterpret_cast<float(*)[4]>(smem_raw + 82944);

    int tid = threadIdx.x;
    int lane = tid & 31, warp = tid >> 5;
    int warpM = warp >> 2, warpN = warp & 3;
    int g = lane >> 2, t = lane & 3;
    int rot = (g & 3) << 3;
    int n0 = blockIdx.x * 128;

    // init Wro3 + sred
    if (tid < 256) {
        int j = tid >> 2, c = tid & 3;
        Wro3[j][c] = (c < 3) ? __ldg(&Wro[j * 64 + c]) : 0.f;
    }
    { int nd = tid >> 2, c = tid & 3; sred[nd][c] = 0.f; }   // 512 = 128*4 exactly

    // ---- gather phase: warp w computes h for nodes [w*8, w*8+8) ----
    {
        float b0 = g_bcmix[lane * 2], b1 = g_bcmix[lane * 2 + 1];
        const float* eb = g_efm + lane * 2;
        for (int q = 0; q < 8; q++) {
            int nl = warp * 8 + q;
            int node = n0 + nl;
            float ax = 0.f, ay = 0.f;
            if (node < NN) {
#pragma unroll
                for (int ty = 0; ty < 2; ty++) {
                    int key = node * 2 + ty;
                    int base = g_offB[key], cnt = g_cntB[key];
                    float sx = 0.f, sy = 0.f;
                    int i = 0;
                    for (; i + 4 <= cnt; i += 4) {
                        int o0 = g_sortB[base + i + 0];
                        int o1 = g_sortB[base + i + 1];
                        int o2 = g_sortB[base + i + 2];
                        int o3 = g_sortB[base + i + 3];
                        float2 v0 = *(const float2*)(eb + o0);
                        float2 v1 = *(const float2*)(eb + o1);
                        float2 v2 = *(const float2*)(eb + o2);
                        float2 v3 = *(const float2*)(eb + o3);
                        sx += (v0.x + v1.x) + (v2.x + v3.x);
                        sy += (v0.y + v1.y) + (v2.y + v3.y);
                    }
                    for (; i < cnt; i++) {
                        int o = g_sortB[base + i];
                        float2 v = *(const float2*)(eb + o);
                        sx += v.x; sy += v.y;
                    }
                    float s = (cnt > 0) ? 1.f / (float)cnt : 0.f;
                    ax += sx * s; ay += sy * s;
                }
            }
            Hs[nl][lane * 2]     = fmaxf(ax + b0, 0.f);
            Hs[nl][lane * 2 + 1] = fmaxf(ay + b1, 0.f);
        }
    }

    // ---- MMA phase: [h | h_prev] @ Bgru (128x256) ----
    float acc[2][8][4] = {};
    for (int kc = 0; kc < 4; kc++) {
        __syncthreads();
        for (int i = tid; i < 4096; i += 512) {
            int m = i >> 5, kk = i & 31;
            int n = n0 + m;
            int kg = kc * 32 + kk;
            float v;
            if (kg < 64) v = Hs[m][kg];
            else         v = (n < NN) ? h_prev[(size_t)n * 64 + kg - 64] : 0.f;
            As[m][swz(kk, m)] = to_tf32(v);
        }
        const float4* src = (const float4*)&g_Bgru[kc * 8192];
        float4* dst = (float4*)&Bs[0][0];
        for (int i = tid; i < 2048; i += 512) dst[i] = src[i];
        __syncthreads();
#pragma unroll
        for (int s = 0; s < 4; s++) {
            int pc = (s * 8 + 2 * t + rot) & 31;
            uint32_t a[2][4];
#pragma unroll
            for (int mt = 0; mt < 2; mt++) {
                int r = warpM * 32 + mt * 16 + g;
                float2 lo = *(const float2*)&As[r][pc];
                float2 hi = *(const float2*)&As[r + 8][pc];
                a[mt][0] = __float_as_uint(lo.x); a[mt][1] = __float_as_uint(hi.x);
                a[mt][2] = __float_as_uint(lo.y); a[mt][3] = __float_as_uint(hi.y);
            }
#pragma unroll
            for (int nt = 0; nt < 8; nt++) {
                int c = warpN * 64 + nt * 8 + g;
                float2 b = *(const float2*)&Bs[c][pc];
                uint32_t b0 = __float_as_uint(b.x), b1 = __float_as_uint(b.y);
                mma_tf32(acc[0][nt], a[0], b0, b1);
                mma_tf32(acc[1][nt], a[1], b0, b1);
            }
        }
    }

    // ---- gate epilogue + fused readout partials ----
    float p[2][2][3] = {};   // [mt][rh][c]
    bool even = (t & 1) == 0;
#pragma unroll
    for (int mt = 0; mt < 2; mt++) {
#pragma unroll
        for (int nt = 0; nt < 8; nt++) {
            int j = warpN * 16 + nt * 2 + (t >> 1);
            float br = g_bias[j], bz = g_bias[64 + j];
            float bn = g_bias[128 + j], bh = g_bias[192 + j];
            float w0 = Wro3[j][0], w1 = Wro3[j][1], w2 = Wro3[j][2];
#pragma unroll
            for (int rh = 0; rh < 2; rh++) {
                int n = n0 + warpM * 32 + mt * 16 + rh * 8 + g;
                float v0 = acc[mt][nt][rh * 2 + 0];
                float v1 = acc[mt][nt][rh * 2 + 1];
                float o0 = __shfl_xor_sync(0xffffffffu, v0, 1);
                float o1 = __shfl_xor_sync(0xffffffffu, v1, 1);
                float hn = 0.f;
                if (even && n < NN) {
                    float r_ = sigf(v0 + br);
                    float z_ = sigf(v1 + bz);
                    float nv = tanh_fast((o0 + bn) + r_ * (o1 + bh));
                    float hp = h_prev[(size_t)n * 64 + j];
                    hn = (1.f - z_) * nv + z_ * hp;
                    out_h[(size_t)n * 64 + j] = hn;
                }
                p[mt][rh][0] += hn * w0;
                p[mt][rh][1] += hn * w1;
                p[mt][rh][2] += hn * w2;
            }
        }
    }
    // reduce t=0 with t=2 lane, then across warpN via smem atomics
#pragma unroll
    for (int mt = 0; mt < 2; mt++)
#pragma unroll
        for (int rh = 0; rh < 2; rh++)
#pragma unroll
            for (int c = 0; c < 3; c++) {
                float v = p[mt][rh][c] + __shfl_xor_sync(0xffffffffu, p[mt][rh][c], 2);
                if (t == 0)
                    atomicAdd(&sred[warpM * 32 + mt * 16 + rh * 8 + g][c], v);
            }
    __syncthreads();
    {
        int nd = tid >> 2, c = tid & 3;
        int n = n0 + nd;
        if (c < 3 && n < NN)
            out3[(size_t)n * 3 + c] = sred[nd][c] + __ldg(&bro[c]);
    }
}

// ---------------- launch -----------------------------------------------------
extern "C" void kernel_launch(void* const* d_in, const int* in_sizes, int n_in,
                              void* d_out, int out_size) {
    const float* x       = (const float*)d_in[0];
    const float* h_prev  = (const float*)d_in[1];
    const int* node_idx  = (const int*)d_in[2];
    const int* hedge_idx = (const int*)d_in[3];
    const int* edge_attr = (const int*)d_in[4];
    const float* W_conv  = (const float*)d_in[5];
    const float* b_conv  = (const float*)d_in[6];
    const float* W_mix   = (const float*)d_in[7];
    const float* b_mix   = (const float*)d_in[8];
    const float* W_ih    = (const float*)d_in[9];
    const float* W_hh    = (const float*)d_in[10];
    const float* b_ih    = (const float*)d_in[11];
    const float* b_hh    = (const float*)d_in[12];
    const float* W_ro    = (const float*)d_in[13];
    const float* b_ro    = (const float*)d_in[14];

    float* h_next = (float*)d_out;
    float* out3   = (float*)d_out + (size_t)NN * 64;

    cudaFuncSetAttribute(k_gru_fused, cudaFuncAttributeMaxDynamicSharedMemorySize,
                         GRU_SMEM);

    k_zero_cnt<<<(NKB + 255) / 256, 256>>>();
    k_prep<<<162, 256>>>(W_conv, W_mix, b_mix, b_conv, W_ih, W_hh, b_ih, b_hh);
    k_hist<<<(NE + 255) / 256, 256>>>(node_idx, hedge_idx, edge_attr);
    k_offsets<<<NBA + NBB, 1024>>>();
    k_perm<<<(NE + 255) / 256, 256>>>(node_idx, hedge_idx, edge_attr);
    k_gatherA<<<(NKA * 32 + 255) / 256, 256>>>(x);
    k_mma_ef<<<dim3((NH + 127) / 128, 2), 256>>>();
    k_gru_fused<<<(NN + 127) / 128, 512, GRU_SMEM>>>(h_prev, W_ro, b_ro, h_next, out3);
}

// round 7
// speedup vs baseline: 1.0480x; 1.0480x over previous
#include <cuda_runtime.h>
#include <cstdint>

#define NN 100000
#define NH 20000
#define NE 800000
#define NKA (NH*2)     // hedge-type keys
#define NKB (NN*2)     // node-type keys
#define NBA ((NKA + 1023) / 1024)
#define NBB ((NKB + 1023) / 1024)

// ---------------- static device buffers ------------------------------------
__device__ __align__(16) float g_aggA[(size_t)2*NH*64];  // (Σx)/cnt per (t,h)
__device__ __align__(16) float g_efm[(size_t)2*NH*64];   // aggA @ Wcomb_t
__device__ __align__(16) float g_h[(size_t)NN*64];       // relu(mix)
__device__ int g_cntA[NKA], g_offA[NKA], g_curA[NKA];
__device__ int g_cntB[NKB], g_offB[NKB], g_curB[NKB];
__device__ int g_baseA, g_baseB;
__device__ int g_sortA[NE];   // node ids, sorted by (hedge,type)
__device__ int g_sortB[NE];   // efm row offsets (floats), sorted by (node,type)
// Pre-swizzled tf32 B-images
__device__ __align__(16) float g_Bef[2*2*64*32];   // Wcomb_t images
__device__ __align__(16) float g_Bgru[4*256*32];
__device__ float g_bias[256];
__device__ float g_bcmix[64];

// ---------------- helpers ---------------------------------------------------
__device__ __forceinline__ float to_tf32(float v) {
    uint32_t u; asm("cvt.rna.tf32.f32 %0, %1;" : "=r"(u) : "f"(v));
    return __uint_as_float(u);
}
__device__ __forceinline__ int swz(int kk, int row) {
    int r = kk & 7;
    int pos = (r < 4) ? (r * 2) : ((r - 4) * 2 + 1);
    int sc = (kk & 24) + pos;
    return (sc + ((row & 3) << 3)) & 31;
}
__device__ __forceinline__ void mma_tf32(float* c, const uint32_t* a,
                                         uint32_t b0, uint32_t b1) {
    asm volatile(
        "mma.sync.aligned.m16n8k8.row.col.f32.tf32.tf32.f32 "
        "{%0,%1,%2,%3}, {%4,%5,%6,%7}, {%8,%9}, {%0,%1,%2,%3};"
        : "+f"(c[0]), "+f"(c[1]), "+f"(c[2]), "+f"(c[3])
        : "r"(a[0]), "r"(a[1]), "r"(a[2]), "r"(a[3]), "r"(b0), "r"(b1));
}
__device__ __forceinline__ float sigf(float x) { return 1.f / (1.f + __expf(-x)); }
__device__ __forceinline__ float tanh_fast(float x) {
    return 1.f - 2.f / (__expf(2.f * x) + 1.f);
}

// ---------------- prep (+ counter zeroing, merged) ---------------------------
__global__ void k_prep(const float* __restrict__ Wc, const float* __restrict__ Wmix,
                       const float* __restrict__ bmix, const float* __restrict__ bconv,
                       const float* __restrict__ Wih, const float* __restrict__ Whh,
                       const float* __restrict__ bih, const float* __restrict__ bhh) {
    int idx = blockIdx.x * blockDim.x + threadIdx.x;
    // zero counters (disjoint outputs from the prep branches below)
    if (idx < NKA) g_cntA[idx] = 0;
    if (idx < NKB) g_cntB[idx] = 0;
    if (idx == 0) { g_baseA = 0; g_baseB = 0; }

    if (idx < 8192) {                     // Bef: [2][2 kc][64 c][32]
        int t = idx >> 12, rem = idx & 4095;
        int kc = rem >> 11, rem2 = rem & 2047, c = rem2 >> 5, kk = rem2 & 31;
        int k = kc * 32 + kk;
        float s = 0.f;
        const float* wr = Wc + t * 4096 + k * 64;
        const float* wm = Wmix + (size_t)t * 64 * 64 + c;
#pragma unroll 8
        for (int m = 0; m < 64; m++) s += wr[m] * wm[(size_t)m * 64];
        g_Bef[((t * 2 + kc) * 64 + c) * 32 + swz(kk, c)] = to_tf32(s);
    } else if (idx < 40960) {             // Bgru: [4][256][32], c = j*4+seg
        int i = idx - 8192;
        int kc = i >> 13, rem = i & 8191, c = rem >> 5, kk = rem & 31;
        int k = kc * 32 + kk;
        int j = c >> 2, seg = c & 3;
        float v = 0.f;
        if (k < 64) {
            if (seg == 0)      v = Wih[k * 192 + j];
            else if (seg == 1) v = Wih[k * 192 + 64 + j];
            else if (seg == 2) v = Wih[k * 192 + 128 + j];
        } else {
            int k2 = k - 64;
            if (seg == 0)      v = Whh[k2 * 192 + j];
            else if (seg == 1) v = Whh[k2 * 192 + 64 + j];
            else if (seg == 3) v = Whh[k2 * 192 + 128 + j];
        }
        g_Bgru[(kc * 256 + c) * 32 + swz(kk, c)] = to_tf32(v);
    } else if (idx < 40960 + 256) {       // GRU bias (seg-major)
        int c = idx - 40960;
        int seg = c >> 6, j = c & 63;
        float b;
        if (seg == 0)      b = bih[j] + bhh[j];
        else if (seg == 1) b = bih[64 + j] + bhh[64 + j];
        else if (seg == 2) b = bih[128 + j];
        else               b = bhh[128 + j];
        g_bias[c] = b;
    } else if (idx < 40960 + 256 + 64) {  // folded mix bias
        int j = idx - 40960 - 256;
        float s = bmix[j];
        for (int k = 0; k < 128; k++) s += bconv[k] * Wmix[k * 64 + j];
        g_bcmix[j] = s;
    }
}

// ---------------- histogram -------------------------------------------------
__global__ void k_hist(const int* __restrict__ ni, const int* __restrict__ hi,
                       const int* __restrict__ ea) {
    int e = blockIdx.x * 256 + threadIdx.x;
    if (e >= NE) return;
    int t = ea[e];
    atomicAdd(&g_cntA[hi[e] * 2 + t], 1);
    atomicAdd(&g_cntB[ni[e] * 2 + t], 1);
}

// ---------------- parallel offsets: block scan + atomic range claim ---------
__global__ __launch_bounds__(1024) void k_offsets() {
    __shared__ int sm[1024];
    __shared__ int blockBase;
    int b = blockIdx.x;
    const int* cnt; int* off; int* cur; int n; int* gbase;
    if (b < NBA) { cnt = g_cntA; off = g_offA; cur = g_curA; n = NKA; gbase = &g_baseA; }
    else { b -= NBA; cnt = g_cntB; off = g_offB; cur = g_curB; n = NKB; gbase = &g_baseB; }
    int tid = threadIdx.x;
    int i = b * 1024 + tid;
    int v = (i < n) ? cnt[i] : 0;
    sm[tid] = v;
    __syncthreads();
    for (int d = 1; d < 1024; d <<= 1) {
        int t = (tid >= d) ? sm[tid - d] : 0;
        __syncthreads();
        sm[tid] += t;
        __syncthreads();
    }
    if (tid == 1023) blockBase = atomicAdd(gbase, sm[1023]);
    __syncthreads();
    if (i < n) {
        int o = blockBase + sm[tid] - v;
        off[i] = o; cur[i] = o;
    }
}

// ---------------- permute: build both sorted lists --------------------------
__global__ void k_perm(const int* __restrict__ ni, const int* __restrict__ hi,
                       const int* __restrict__ ea) {
    int e = blockIdx.x * 256 + threadIdx.x;
    if (e >= NE) return;
    int n = ni[e], h = hi[e], t = ea[e];
    int pA = atomicAdd(&g_curA[h * 2 + t], 1);
    g_sortA[pA] = n;
    int pB = atomicAdd(&g_curB[n * 2 + t], 1);
    g_sortB[pB] = (t * NH + h) * 64;
}

// ---------------- gather A: aggA[t,h] = (1/cnt) * sum x[node] ----------------
__global__ __launch_bounds__(256) void k_gatherA(const float* __restrict__ x) {
    int key = (blockIdx.x * 256 + threadIdx.x) >> 5;
    if (key >= NKA) return;
    int lane = threadIdx.x & 31;
    int t = key & 1, h = key >> 1;
    int base = g_offA[key], cnt = g_cntA[key];
    const float* xb = x + lane * 2;
    float ax = 0.f, ay = 0.f;
    int i = 0;
    for (; i + 4 <= cnt; i += 4) {
        int n0 = g_sortA[base + i + 0];
        int n1 = g_sortA[base + i + 1];
        int n2 = g_sortA[base + i + 2];
        int n3 = g_sortA[base + i + 3];
        float2 v0 = *(const float2*)(xb + (size_t)n0 * 64);
        float2 v1 = *(const float2*)(xb + (size_t)n1 * 64);
        float2 v2 = *(const float2*)(xb + (size_t)n2 * 64);
        float2 v3 = *(const float2*)(xb + (size_t)n3 * 64);
        ax += (v0.x + v1.x) + (v2.x + v3.x);
        ay += (v0.y + v1.y) + (v2.y + v3.y);
    }
    for (; i < cnt; i++) {
        int n = g_sortA[base + i];
        float2 v = *(const float2*)(xb + (size_t)n * 64);
        ax += v.x; ay += v.y;
    }
    float s = (cnt > 0) ? 1.f / (float)cnt : 0.f;
    *(float2*)&g_aggA[((size_t)t * NH + h) * 64 + lane * 2] = make_float2(ax * s, ay * s);
}

// ---------------- GEMM: efm = aggA @ Wcomb_t   (M=NH per type, N=64, K=64) --
__global__ __launch_bounds__(256) void k_mma_ef() {
    __shared__ __align__(16) float As[128][32];
    __shared__ __align__(16) float Bs[64][32];
    int tid = threadIdx.x;
    int lane = tid & 31, warp = tid >> 5;
    int warpM = warp >> 1, warpN = warp & 1;
    int g = lane >> 2, t4 = lane & 3;
    int rot = (g & 3) << 3;
    int n0 = blockIdx.x * 128;
    int ty = blockIdx.y;
    float acc[2][4][4] = {};
    for (int kc = 0; kc < 2; kc++) {
        __syncthreads();
        for (int i = tid; i < 4096; i += 256) {
            int m = i >> 5, kk = i & 31;
            int n = n0 + m;
            float v = (n < NH) ? g_aggA[((size_t)ty * NH + n) * 64 + kc * 32 + kk] : 0.f;
            As[m][swz(kk, m)] = to_tf32(v);
        }
        const float4* src = (const float4*)&g_Bef[(ty * 2 + kc) * 2048];
        float4* dst = (float4*)&Bs[0][0];
        for (int i = tid; i < 512; i += 256) dst[i] = src[i];
        __syncthreads();
#pragma unroll
        for (int s = 0; s < 4; s++) {
            int pc = (s * 8 + 2 * t4 + rot) & 31;
            uint32_t a[2][4];
#pragma unroll
            for (int mt = 0; mt < 2; mt++) {
                int r = warpM * 32 + mt * 16 + g;
                float2 lo = *(const float2*)&As[r][pc];
                float2 hi = *(const float2*)&As[r + 8][pc];
                a[mt][0] = __float_as_uint(lo.x); a[mt][1] = __float_as_uint(hi.x);
                a[mt][2] = __float_as_uint(lo.y); a[mt][3] = __float_as_uint(hi.y);
            }
#pragma unroll
            for (int nt = 0; nt < 4; nt++) {
                int c = warpN * 32 + nt * 8 + g;
                float2 b = *(const float2*)&Bs[c][pc];
                uint32_t b0 = __float_as_uint(b.x), b1 = __float_as_uint(b.y);
                mma_tf32(acc[0][nt], a[0], b0, b1);
                mma_tf32(acc[1][nt], a[1], b0, b1);
            }
        }
    }
#pragma unroll
    for (int mt = 0; mt < 2; mt++) {
        int r = n0 + warpM * 32 + mt * 16 + g;
#pragma unroll
        for (int nt = 0; nt < 4; nt++) {
            int c = warpN * 32 + nt * 8 + 2 * t4;
            if (r < NH)
                *(float2*)&g_efm[((size_t)ty * NH + r) * 64 + c] =
                    make_float2(acc[mt][nt][0], acc[mt][nt][1]);
            if (r + 8 < NH)
                *(float2*)&g_efm[((size_t)ty * NH + r + 8) * 64 + c] =
                    make_float2(acc[mt][nt][2], acc[mt][nt][3]);
        }
    }
}

// ---------------- gather B: h[n] = relu(sum_t Dinv_t * sum efm + bcmix) -----
__global__ __launch_bounds__(256) void k_gatherB() {
    int node = (blockIdx.x * 256 + threadIdx.x) >> 5;
    if (node >= NN) return;
    int lane = threadIdx.x & 31;
    const float* eb = g_efm + lane * 2;
    float ax = 0.f, ay = 0.f;
#pragma unroll
    for (int t = 0; t < 2; t++) {
        int key = node * 2 + t;
        int base = g_offB[key], cnt = g_cntB[key];
        float sx = 0.f, sy = 0.f;
        int i = 0;
        for (; i + 4 <= cnt; i += 4) {
            int o0 = g_sortB[base + i + 0];
            int o1 = g_sortB[base + i + 1];
            int o2 = g_sortB[base + i + 2];
            int o3 = g_sortB[base + i + 3];
            float2 v0 = *(const float2*)(eb + o0);
            float2 v1 = *(const float2*)(eb + o1);
            float2 v2 = *(const float2*)(eb + o2);
            float2 v3 = *(const float2*)(eb + o3);
            sx += (v0.x + v1.x) + (v2.x + v3.x);
            sy += (v0.y + v1.y) + (v2.y + v3.y);
        }
        for (; i < cnt; i++) {
            int o = g_sortB[base + i];
            float2 v = *(const float2*)(eb + o);
            sx += v.x; sy += v.y;
        }
        float s = (cnt > 0) ? 1.f / (float)cnt : 0.f;
        ax += sx * s; ay += sy * s;
    }
    float b0 = g_bcmix[lane * 2], b1 = g_bcmix[lane * 2 + 1];
    *(float2*)&g_h[(size_t)node * 64 + lane * 2] =
        make_float2(fmaxf(ax + b0, 0.f), fmaxf(ay + b1, 0.f));
}

// ---------------- GRU GEMM + gates + fused readout --------------------------
// dyn smem: As[128][32] 16KB | Bs[256][32] 32KB | Wro3[64][4] 1KB | sred[128][4] 2KB
#define GRU_SMEM (16384 + 32768 + 1024 + 2048)
__global__ __launch_bounds__(512) void k_gru(const float* __restrict__ h_prev,
                                             const float* __restrict__ Wro,
                                             const float* __restrict__ bro,
                                             float* __restrict__ out_h,
                                             float* __restrict__ out3) {
    extern __shared__ __align__(16) char smem_raw[];
    float (*As)[32]  = reinterpret_cast<float(*)[32]>(smem_raw);
    float (*Bs)[32]  = reinterpret_cast<float(*)[32]>(smem_raw + 16384);
    float (*Wro3)[4] = reinterpret_cast<float(*)[4]>(smem_raw + 49152);
    float (*sred)[4] = reinterpret_cast<float(*)[4]>(smem_raw + 50176);

    int tid = threadIdx.x;
    int lane = tid & 31, warp = tid >> 5;
    int warpM = warp >> 2, warpN = warp & 3;
    int g = lane >> 2, t = lane & 3;
    int rot = (g & 3) << 3;
    int n0 = blockIdx.x * 128;

    if (tid < 256) {
        int j = tid >> 2, c = tid & 3;
        Wro3[j][c] = (c < 3) ? __ldg(&Wro[j * 64 + c]) : 0.f;
    }
    { int nd = tid >> 2, c = tid & 3; sred[nd][c] = 0.f; }   // 512 = 128*4

    float acc[2][8][4] = {};
    for (int kc = 0; kc < 4; kc++) {
        __syncthreads();
        for (int i = tid; i < 4096; i += 512) {
            int m = i >> 5, kk = i & 31;
            int n = n0 + m;
            int kg = kc * 32 + kk;
            float v = 0.f;
            if (n < NN)
                v = (kg < 64) ? g_h[(size_t)n * 64 + kg]
                              : h_prev[(size_t)n * 64 + kg - 64];
            As[m][swz(kk, m)] = to_tf32(v);
        }
        const float4* src = (const float4*)&g_Bgru[kc * 8192];
        float4* dst = (float4*)&Bs[0][0];
        for (int i = tid; i < 2048; i += 512) dst[i] = src[i];
        __syncthreads();
#pragma unroll
        for (int s = 0; s < 4; s++) {
            int pc = (s * 8 + 2 * t + rot) & 31;
            uint32_t a[2][4];
#pragma unroll
            for (int mt = 0; mt < 2; mt++) {
                int r = warpM * 32 + mt * 16 + g;
                float2 lo = *(const float2*)&As[r][pc];
                float2 hi = *(const float2*)&As[r + 8][pc];
                a[mt][0] = __float_as_uint(lo.x); a[mt][1] = __float_as_uint(hi.x);
                a[mt][2] = __float_as_uint(lo.y); a[mt][3] = __float_as_uint(hi.y);
            }
#pragma unroll
            for (int nt = 0; nt < 8; nt++) {
                int c = warpN * 64 + nt * 8 + g;
                float2 b = *(const float2*)&Bs[c][pc];
                uint32_t b0 = __float_as_uint(b.x), b1 = __float_as_uint(b.y);
                mma_tf32(acc[0][nt], a[0], b0, b1);
                mma_tf32(acc[1][nt], a[1], b0, b1);
            }
        }
    }

    // ---- gate epilogue + fused readout partials ----
    float p[2][2][3] = {};
    bool even = (t & 1) == 0;
#pragma unroll
    for (int mt = 0; mt < 2; mt++) {
#pragma unroll
        for (int nt = 0; nt < 8; nt++) {
            int j = warpN * 16 + nt * 2 + (t >> 1);
            float br = g_bias[j], bz = g_bias[64 + j];
            float bn = g_bias[128 + j], bh = g_bias[192 + j];
            float w0 = Wro3[j][0], w1 = Wro3[j][1], w2 = Wro3[j][2];
#pragma unroll
            for (int rh = 0; rh < 2; rh++) {
                int n = n0 + warpM * 32 + mt * 16 + rh * 8 + g;
                float v0 = acc[mt][nt][rh * 2 + 0];
                float v1 = acc[mt][nt][rh * 2 + 1];
                float o0 = __shfl_xor_sync(0xffffffffu, v0, 1);
                float o1 = __shfl_xor_sync(0xffffffffu, v1, 1);
                float hn = 0.f;
                if (even && n < NN) {
                    float r_ = sigf(v0 + br);
                    float z_ = sigf(v1 + bz);
                    float nv = tanh_fast((o0 + bn) + r_ * (o1 + bh));
                    float hp = h_prev[(size_t)n * 64 + j];
                    hn = (1.f - z_) * nv + z_ * hp;
                    out_h[(size_t)n * 64 + j] = hn;
                }
                p[mt][rh][0] += hn * w0;
                p[mt][rh][1] += hn * w1;
                p[mt][rh][2] += hn * w2;
            }
        }
    }
#pragma unroll
    for (int mt = 0; mt < 2; mt++)
#pragma unroll
        for (int rh = 0; rh < 2; rh++)
#pragma unroll
            for (int c = 0; c < 3; c++) {
                float v = p[mt][rh][c] + __shfl_xor_sync(0xffffffffu, p[mt][rh][c], 2);
                if (t == 0)
                    atomicAdd(&sred[warpM * 32 + mt * 16 + rh * 8 + g][c], v);
            }
    __syncthreads();
    {
        int nd = tid >> 2, c = tid & 3;
        int n = n0 + nd;
        if (c < 3 && n < NN)
            out3[(size_t)n * 3 + c] = sred[nd][c] + __ldg(&bro[c]);
    }
}

// ---------------- launch -----------------------------------------------------
extern "C" void kernel_launch(void* const* d_in, const int* in_sizes, int n_in,
                              void* d_out, int out_size) {
    const float* x       = (const float*)d_in[0];
    const float* h_prev  = (const float*)d_in[1];
    const int* node_idx  = (const int*)d_in[2];
    const int* hedge_idx = (const int*)d_in[3];
    const int* edge_attr = (const int*)d_in[4];
    const float* W_conv  = (const float*)d_in[5];
    const float* b_conv  = (const float*)d_in[6];
    const float* W_mix   = (const float*)d_in[7];
    const float* b_mix   = (const float*)d_in[8];
    const float* W_ih    = (const float*)d_in[9];
    const float* W_hh    = (const float*)d_in[10];
    const float* b_ih    = (const float*)d_in[11];
    const float* b_hh    = (const float*)d_in[12];
    const float* W_ro    = (const float*)d_in[13];
    const float* b_ro    = (const float*)d_in[14];

    float* h_next = (float*)d_out;
    float* out3   = (float*)d_out + (size_t)NN * 64;

    cudaFuncSetAttribute(k_gru, cudaFuncAttributeMaxDynamicSharedMemorySize, GRU_SMEM);

    k_prep<<<(NKB + 255) / 256, 256>>>(W_conv, W_mix, b_mix, b_conv,
                                       W_ih, W_hh, b_ih, b_hh);
    k_hist<<<(NE + 255) / 256, 256>>>(node_idx, hedge_idx, edge_attr);
    k_offsets<<<NBA + NBB, 1024>>>();
    k_perm<<<(NE + 255) / 256, 256>>>(node_idx, hedge_idx, edge_attr);
    k_gatherA<<<(NKA * 32 + 255) / 256, 256>>>(x);
    k_mma_ef<<<dim3((NH + 127) / 128, 2), 256>>>();
    k_gatherB<<<(NN * 32 + 255) / 256, 256>>>();
    k_gru<<<(NN + 127) / 128, 512, GRU_SMEM>>>(h_prev, W_ro, b_ro, h_next, out3);
}

// round 8
// speedup vs baseline: 1.0804x; 1.0309x over previous
#include <cuda_runtime.h>
#include <cstdint>

#define NN 100000
#define NH 20000
#define NE 800000
#define NE4 (NE/4)
#define NKA (NH*2)     // hedge-type keys
#define NKB (NN*2)     // node-type keys
#define NBA ((NKA + 1023) / 1024)
#define NBB ((NKB + 1023) / 1024)

// ---------------- static device buffers ------------------------------------
__device__ __align__(16) float g_aggA[(size_t)2*NH*64];  // (Σx)/cnt per (t,h)
__device__ __align__(16) float g_efm[(size_t)2*NH*64];   // aggA @ Wcomb_t
__device__ __align__(16) float g_h[(size_t)NN*64];       // relu(mix)
__device__ int g_cntA[NKA], g_offA[NKA];
__device__ int g_cntB[NKB], g_offB[NKB];
__device__ int g_baseA, g_baseB;
__device__ __align__(16) int g_rankA[NE], g_rankB[NE];
__device__ int g_sortA[NE];   // node ids, sorted by (hedge,type)
__device__ int g_sortB[NE];   // efm row offsets (floats), sorted by (node,type)
// Pre-swizzled tf32 B-images
__device__ __align__(16) float g_Bef[2*2*64*32];   // Wcomb_t images
__device__ __align__(16) float g_Bgru[4*256*32];
__device__ float g_bias[256];
__device__ float g_bcmix[64];

// ---------------- helpers ---------------------------------------------------
__device__ __forceinline__ float to_tf32(float v) {
    uint32_t u; asm("cvt.rna.tf32.f32 %0, %1;" : "=r"(u) : "f"(v));
    return __uint_as_float(u);
}
__device__ __forceinline__ int swz(int kk, int row) {
    int r = kk & 7;
    int pos = (r < 4) ? (r * 2) : ((r - 4) * 2 + 1);
    int sc = (kk & 24) + pos;
    return (sc + ((row & 3) << 3)) & 31;
}
__device__ __forceinline__ void mma_tf32(float* c, const uint32_t* a,
                                         uint32_t b0, uint32_t b1) {
    asm volatile(
        "mma.sync.aligned.m16n8k8.row.col.f32.tf32.tf32.f32 "
        "{%0,%1,%2,%3}, {%4,%5,%6,%7}, {%8,%9}, {%0,%1,%2,%3};"
        : "+f"(c[0]), "+f"(c[1]), "+f"(c[2]), "+f"(c[3])
        : "r"(a[0]), "r"(a[1]), "r"(a[2]), "r"(a[3]), "r"(b0), "r"(b1));
}
__device__ __forceinline__ float sigf(float x) { return 1.f / (1.f + __expf(-x)); }
__device__ __forceinline__ float tanh_fast(float x) {
    return 1.f - 2.f / (__expf(2.f * x) + 1.f);
}

// ---------------- prep (+ counter zeroing, merged) ---------------------------
__global__ void k_prep(const float* __restrict__ Wc, const float* __restrict__ Wmix,
                       const float* __restrict__ bmix, const float* __restrict__ bconv,
                       const float* __restrict__ Wih, const float* __restrict__ Whh,
                       const float* __restrict__ bih, const float* __restrict__ bhh) {
    int idx = blockIdx.x * blockDim.x + threadIdx.x;
    if (idx < NKA) g_cntA[idx] = 0;
    if (idx < NKB) g_cntB[idx] = 0;
    if (idx == 0) { g_baseA = 0; g_baseB = 0; }

    if (idx < 8192) {                     // Bef: [2][2 kc][64 c][32]
        int t = idx >> 12, rem = idx & 4095;
        int kc = rem >> 11, rem2 = rem & 2047, c = rem2 >> 5, kk = rem2 & 31;
        int k = kc * 32 + kk;
        float s = 0.f;
        const float* wr = Wc + t * 4096 + k * 64;
        const float* wm = Wmix + (size_t)t * 64 * 64 + c;
#pragma unroll 8
        for (int m = 0; m < 64; m++) s += wr[m] * wm[(size_t)m * 64];
        g_Bef[((t * 2 + kc) * 64 + c) * 32 + swz(kk, c)] = to_tf32(s);
    } else if (idx < 40960) {             // Bgru: [4][256][32], c = j*4+seg
        int i = idx - 8192;
        int kc = i >> 13, rem = i & 8191, c = rem >> 5, kk = rem & 31;
        int k = kc * 32 + kk;
        int j = c >> 2, seg = c & 3;
        float v = 0.f;
        if (k < 64) {
            if (seg == 0)      v = Wih[k * 192 + j];
            else if (seg == 1) v = Wih[k * 192 + 64 + j];
            else if (seg == 2) v = Wih[k * 192 + 128 + j];
        } else {
            int k2 = k - 64;
            if (seg == 0)      v = Whh[k2 * 192 + j];
            else if (seg == 1) v = Whh[k2 * 192 + 64 + j];
            else if (seg == 3) v = Whh[k2 * 192 + 128 + j];
        }
        g_Bgru[(kc * 256 + c) * 32 + swz(kk, c)] = to_tf32(v);
    } else if (idx < 40960 + 256) {       // GRU bias (seg-major)
        int c = idx - 40960;
        int seg = c >> 6, j = c & 63;
        float b;
        if (seg == 0)      b = bih[j] + bhh[j];
        else if (seg == 1) b = bih[64 + j] + bhh[64 + j];
        else if (seg == 2) b = bih[128 + j];
        else               b = bhh[128 + j];
        g_bias[c] = b;
    } else if (idx < 40960 + 256 + 64) {  // folded mix bias
        int j = idx - 40960 - 256;
        float s = bmix[j];
        for (int k = 0; k < 128; k++) s += bconv[k] * Wmix[k * 64 + j];
        g_bcmix[j] = s;
    }
}

// ---------------- histogram + rank capture (int4, 4 edges/thread) -----------
__global__ void k_hist(const int* __restrict__ ni, const int* __restrict__ hi,
                       const int* __restrict__ ea) {
    int i = blockIdx.x * 256 + threadIdx.x;
    if (i >= NE4) return;
    int4 n = ((const int4*)ni)[i];
    int4 h = ((const int4*)hi)[i];
    int4 t = ((const int4*)ea)[i];
    int4 ra, rb;
    ra.x = atomicAdd(&g_cntA[h.x * 2 + t.x], 1);
    ra.y = atomicAdd(&g_cntA[h.y * 2 + t.y], 1);
    ra.z = atomicAdd(&g_cntA[h.z * 2 + t.z], 1);
    ra.w = atomicAdd(&g_cntA[h.w * 2 + t.w], 1);
    rb.x = atomicAdd(&g_cntB[n.x * 2 + t.x], 1);
    rb.y = atomicAdd(&g_cntB[n.y * 2 + t.y], 1);
    rb.z = atomicAdd(&g_cntB[n.z * 2 + t.z], 1);
    rb.w = atomicAdd(&g_cntB[n.w * 2 + t.w], 1);
    ((int4*)g_rankA)[i] = ra;
    ((int4*)g_rankB)[i] = rb;
}

// ---------------- parallel offsets: block scan + atomic range claim ---------
__global__ __launch_bounds__(1024) void k_offsets() {
    __shared__ int sm[1024];
    __shared__ int blockBase;
    int b = blockIdx.x;
    const int* cnt; int* off; int n; int* gbase;
    if (b < NBA) { cnt = g_cntA; off = g_offA; n = NKA; gbase = &g_baseA; }
    else { b -= NBA; cnt = g_cntB; off = g_offB; n = NKB; gbase = &g_baseB; }
    int tid = threadIdx.x;
    int i = b * 1024 + tid;
    int v = (i < n) ? cnt[i] : 0;
    sm[tid] = v;
    __syncthreads();
    for (int d = 1; d < 1024; d <<= 1) {
        int t = (tid >= d) ? sm[tid - d] : 0;
        __syncthreads();
        sm[tid] += t;
        __syncthreads();
    }
    if (tid == 1023) blockBase = atomicAdd(gbase, sm[1023]);
    __syncthreads();
    if (i < n) off[i] = blockBase + sm[tid] - v;
}

// ---------------- permute: atomic-free scatter using captured ranks ---------
__global__ void k_perm(const int* __restrict__ ni, const int* __restrict__ hi,
                       const int* __restrict__ ea) {
    int i = blockIdx.x * 256 + threadIdx.x;
    if (i >= NE4) return;
    int4 n = ((const int4*)ni)[i];
    int4 h = ((const int4*)hi)[i];
    int4 t = ((const int4*)ea)[i];
    int4 ra = ((const int4*)g_rankA)[i];
    int4 rb = ((const int4*)g_rankB)[i];
    g_sortA[g_offA[h.x * 2 + t.x] + ra.x] = n.x;
    g_sortA[g_offA[h.y * 2 + t.y] + ra.y] = n.y;
    g_sortA[g_offA[h.z * 2 + t.z] + ra.z] = n.z;
    g_sortA[g_offA[h.w * 2 + t.w] + ra.w] = n.w;
    g_sortB[g_offB[n.x * 2 + t.x] + rb.x] = (t.x * NH + h.x) * 64;
    g_sortB[g_offB[n.y * 2 + t.y] + rb.y] = (t.y * NH + h.y) * 64;
    g_sortB[g_offB[n.z * 2 + t.z] + rb.z] = (t.z * NH + h.z) * 64;
    g_sortB[g_offB[n.w * 2 + t.w] + rb.w] = (t.w * NH + h.w) * 64;
}

// ---------------- gather A: aggA[t,h] = (1/cnt) * sum x[node] ----------------
__global__ __launch_bounds__(256) void k_gatherA(const float* __restrict__ x) {
    int key = (blockIdx.x * 256 + threadIdx.x) >> 5;
    if (key >= NKA) return;
    int lane = threadIdx.x & 31;
    int t = key & 1, h = key >> 1;
    int base = g_offA[key], cnt = g_cntA[key];
    const float* xb = x + lane * 2;
    float ax = 0.f, ay = 0.f;
    int i = 0;
    for (; i + 8 <= cnt; i += 8) {
        float2 v[8];
#pragma unroll
        for (int q = 0; q < 8; q++) {
            int n = g_sortA[base + i + q];
            v[q] = *(const float2*)(xb + (size_t)n * 64);
        }
#pragma unroll
        for (int q = 0; q < 8; q++) { ax += v[q].x; ay += v[q].y; }
    }
    for (; i < cnt; i++) {
        int n = g_sortA[base + i];
        float2 v = *(const float2*)(xb + (size_t)n * 64);
        ax += v.x; ay += v.y;
    }
    float s = (cnt > 0) ? 1.f / (float)cnt : 0.f;
    *(float2*)&g_aggA[((size_t)t * NH + h) * 64 + lane * 2] = make_float2(ax * s, ay * s);
}

// ---------------- GEMM: efm = aggA @ Wcomb_t   (M=NH per type, N=64, K=64) --
__global__ __launch_bounds__(256) void k_mma_ef() {
    __shared__ __align__(16) float As[128][32];
    __shared__ __align__(16) float Bs[64][32];
    int tid = threadIdx.x;
    int lane = tid & 31, warp = tid >> 5;
    int warpM = warp >> 1, warpN = warp & 1;
    int g = lane >> 2, t4 = lane & 3;
    int rot = (g & 3) << 3;
    int n0 = blockIdx.x * 128;
    int ty = blockIdx.y;
    float acc[2][4][4] = {};
    for (int kc = 0; kc < 2; kc++) {
        __syncthreads();
        for (int i = tid; i < 4096; i += 256) {
            int m = i >> 5, kk = i & 31;
            int n = n0 + m;
            float v = (n < NH) ? g_aggA[((size_t)ty * NH + n) * 64 + kc * 32 + kk] : 0.f;
            As[m][swz(kk, m)] = to_tf32(v);
        }
        const float4* src = (const float4*)&g_Bef[(ty * 2 + kc) * 2048];
        float4* dst = (float4*)&Bs[0][0];
        for (int i = tid; i < 512; i += 256) dst[i] = src[i];
        __syncthreads();
#pragma unroll
        for (int s = 0; s < 4; s++) {
            int pc = (s * 8 + 2 * t4 + rot) & 31;
            uint32_t a[2][4];
#pragma unroll
            for (int mt = 0; mt < 2; mt++) {
                int r = warpM * 32 + mt * 16 + g;
                float2 lo = *(const float2*)&As[r][pc];
                float2 hi = *(const float2*)&As[r + 8][pc];
                a[mt][0] = __float_as_uint(lo.x); a[mt][1] = __float_as_uint(hi.x);
                a[mt][2] = __float_as_uint(lo.y); a[mt][3] = __float_as_uint(hi.y);
            }
#pragma unroll
            for (int nt = 0; nt < 4; nt++) {
                int c = warpN * 32 + nt * 8 + g;
                float2 b = *(const float2*)&Bs[c][pc];
                uint32_t b0 = __float_as_uint(b.x), b1 = __float_as_uint(b.y);
                mma_tf32(acc[0][nt], a[0], b0, b1);
                mma_tf32(acc[1][nt], a[1], b0, b1);
            }
        }
    }
#pragma unroll
    for (int mt = 0; mt < 2; mt++) {
        int r = n0 + warpM * 32 + mt * 16 + g;
#pragma unroll
        for (int nt = 0; nt < 4; nt++) {
            int c = warpN * 32 + nt * 8 + 2 * t4;
            if (r < NH)
                *(float2*)&g_efm[((size_t)ty * NH + r) * 64 + c] =
                    make_float2(acc[mt][nt][0], acc[mt][nt][1]);
            if (r + 8 < NH)
                *(float2*)&g_efm[((size_t)ty * NH + r + 8) * 64 + c] =
                    make_float2(acc[mt][nt][2], acc[mt][nt][3]);
        }
    }
}

// ---------------- gather B: h[n] = relu(sum_t Dinv_t * sum efm + bcmix) -----
__global__ __launch_bounds__(256) void k_gatherB() {
    int node = (blockIdx.x * 256 + threadIdx.x) >> 5;
    if (node >= NN) return;
    int lane = threadIdx.x & 31;
    const float* eb = g_efm + lane * 2;
    float ax = 0.f, ay = 0.f;
#pragma unroll
    for (int t = 0; t < 2; t++) {
        int key = node * 2 + t;
        int base = g_offB[key], cnt = g_cntB[key];
        float sx = 0.f, sy = 0.f;
        int i = 0;
        for (; i + 8 <= cnt; i += 8) {
            float2 v[8];
#pragma unroll
            for (int q = 0; q < 8; q++) {
                int o = g_sortB[base + i + q];
                v[q] = *(const float2*)(eb + o);
            }
#pragma unroll
            for (int q = 0; q < 8; q++) { sx += v[q].x; sy += v[q].y; }
        }
        for (; i < cnt; i++) {
            int o = g_sortB[base + i];
            float2 v = *(const float2*)(eb + o);
            sx += v.x; sy += v.y;
        }
        float s = (cnt > 0) ? 1.f / (float)cnt : 0.f;
        ax += sx * s; ay += sy * s;
    }
    float b0 = g_bcmix[lane * 2], b1 = g_bcmix[lane * 2 + 1];
    *(float2*)&g_h[(size_t)node * 64 + lane * 2] =
        make_float2(fmaxf(ax + b0, 0.f), fmaxf(ay + b1, 0.f));
}

// ---------------- GRU GEMM + gates + fused readout --------------------------
#define GRU_SMEM (16384 + 32768 + 1024 + 2048)
__global__ __launch_bounds__(512) void k_gru(const float* __restrict__ h_prev,
                                             const float* __restrict__ Wro,
                                             const float* __restrict__ bro,
                                             float* __restrict__ out_h,
                                             float* __restrict__ out3) {
    extern __shared__ __align__(16) char smem_raw[];
    float (*As)[32]  = reinterpret_cast<float(*)[32]>(smem_raw);
    float (*Bs)[32]  = reinterpret_cast<float(*)[32]>(smem_raw + 16384);
    float (*Wro3)[4] = reinterpret_cast<float(*)[4]>(smem_raw + 49152);
    float (*sred)[4] = reinterpret_cast<float(*)[4]>(smem_raw + 50176);

    int tid = threadIdx.x;
    int lane = tid & 31, warp = tid >> 5;
    int warpM = warp >> 2, warpN = warp & 3;
    int g = lane >> 2, t = lane & 3;
    int rot = (g & 3) << 3;
    int n0 = blockIdx.x * 128;

    if (tid < 256) {
        int j = tid >> 2, c = tid & 3;
        Wro3[j][c] = (c < 3) ? __ldg(&Wro[j * 64 + c]) : 0.f;
    }
    { int nd = tid >> 2, c = tid & 3; sred[nd][c] = 0.f; }

    float acc[2][8][4] = {};
    for (int kc = 0; kc < 4; kc++) {
        __syncthreads();
        for (int i = tid; i < 4096; i += 512) {
            int m = i >> 5, kk = i & 31;
            int n = n0 + m;
            int kg = kc * 32 + kk;
            float v = 0.f;
            if (n < NN)
                v = (kg < 64) ? g_h[(size_t)n * 64 + kg]
                              : h_prev[(size_t)n * 64 + kg - 64];
            As[m][swz(kk, m)] = to_tf32(v);
        }
        const float4* src = (const float4*)&g_Bgru[kc * 8192];
        float4* dst = (float4*)&Bs[0][0];
        for (int i = tid; i < 2048; i += 512) dst[i] = src[i];
        __syncthreads();
#pragma unroll
        for (int s = 0; s < 4; s++) {
            int pc = (s * 8 + 2 * t + rot) & 31;
            uint32_t a[2][4];
#pragma unroll
            for (int mt = 0; mt < 2; mt++) {
                int r = warpM * 32 + mt * 16 + g;
                float2 lo = *(const float2*)&As[r][pc];
                float2 hi = *(const float2*)&As[r + 8][pc];
                a[mt][0] = __float_as_uint(lo.x); a[mt][1] = __float_as_uint(hi.x);
                a[mt][2] = __float_as_uint(lo.y); a[mt][3] = __float_as_uint(hi.y);
            }
#pragma unroll
            for (int nt = 0; nt < 8; nt++) {
                int c = warpN * 64 + nt * 8 + g;
                float2 b = *(const float2*)&Bs[c][pc];
                uint32_t b0 = __float_as_uint(b.x), b1 = __float_as_uint(b.y);
                mma_tf32(acc[0][nt], a[0], b0, b1);
                mma_tf32(acc[1][nt], a[1], b0, b1);
            }
        }
    }

    float p[2][2][3] = {};
    bool even = (t & 1) == 0;
#pragma unroll
    for (int mt = 0; mt < 2; mt++) {
#pragma unroll
        for (int nt = 0; nt < 8; nt++) {
            int j = warpN * 16 + nt * 2 + (t >> 1);
            float br = g_bias[j], bz = g_bias[64 + j];
            float bn = g_bias[128 + j], bh = g_bias[192 + j];
            float w0 = Wro3[j][0], w1 = Wro3[j][1], w2 = Wro3[j][2];
#pragma unroll
            for (int rh = 0; rh < 2; rh++) {
                int n = n0 + warpM * 32 + mt * 16 + rh * 8 + g;
                float v0 = acc[mt][nt][rh * 2 + 0];
                float v1 = acc[mt][nt][rh * 2 + 1];
                float o0 = __shfl_xor_sync(0xffffffffu, v0, 1);
                float o1 = __shfl_xor_sync(0xffffffffu, v1, 1);
                float hn = 0.f;
                if (even && n < NN) {
                    float r_ = sigf(v0 + br);
                    float z_ = sigf(v1 + bz);
                    float nv = tanh_fast((o0 + bn) + r_ * (o1 + bh));
                    float hp = h_prev[(size_t)n * 64 + j];
                    hn = (1.f - z_) * nv + z_ * hp;
                    out_h[(size_t)n * 64 + j] = hn;
                }
                p[mt][rh][0] += hn * w0;
                p[mt][rh][1] += hn * w1;
                p[mt][rh][2] += hn * w2;
            }
        }
    }
#pragma unroll
    for (int mt = 0; mt < 2; mt++)
#pragma unroll
        for (int rh = 0; rh < 2; rh++)
#pragma unroll
            for (int c = 0; c < 3; c++) {
                float v = p[mt][rh][c] + __shfl_xor_sync(0xffffffffu, p[mt][rh][c], 2);
                if (t == 0)
                    atomicAdd(&sred[warpM * 32 + mt * 16 + rh * 8 + g][c], v);
            }
    __syncthreads();
    {
        int nd = tid >> 2, c = tid & 3;
        int n = n0 + nd;
        if (c < 3 && n < NN)
            out3[(size_t)n * 3 + c] = sred[nd][c] + __ldg(&bro[c]);
    }
}

// ---------------- launch -----------------------------------------------------
extern "C" void kernel_launch(void* const* d_in, const int* in_sizes, int n_in,
                              void* d_out, int out_size) {
    const float* x       = (const float*)d_in[0];
    const float* h_prev  = (const float*)d_in[1];
    const int* node_idx  = (const int*)d_in[2];
    const int* hedge_idx = (const int*)d_in[3];
    const int* edge_attr = (const int*)d_in[4];
    const float* W_conv  = (const float*)d_in[5];
    const float* b_conv  = (const float*)d_in[6];
    const float* W_mix   = (const float*)d_in[7];
    const float* b_mix   = (const float*)d_in[8];
    const float* W_ih    = (const float*)d_in[9];
    const float* W_hh    = (const float*)d_in[10];
    const float* b_ih    = (const float*)d_in[11];
    const float* b_hh    = (const float*)d_in[12];
    const float* W_ro    = (const float*)d_in[13];
    const float* b_ro    = (const float*)d_in[14];

    float* h_next = (float*)d_out;
    float* out3   = (float*)d_out + (size_t)NN * 64;

    cudaFuncSetAttribute(k_gru, cudaFuncAttributeMaxDynamicSharedMemorySize, GRU_SMEM);

    k_prep<<<(NKB + 255) / 256, 256>>>(W_conv, W_mix, b_mix, b_conv,
                                       W_ih, W_hh, b_ih, b_hh);
    k_hist<<<(NE4 + 255) / 256, 256>>>(node_idx, hedge_idx, edge_attr);
    k_offsets<<<NBA + NBB, 1024>>>();
    k_perm<<<(NE4 + 255) / 256, 256>>>(node_idx, hedge_idx, edge_attr);
    k_gatherA<<<(NKA * 32 + 255) / 256, 256>>>(x);
    k_mma_ef<<<dim3((NH + 127) / 128, 2), 256>>>();
    k_gatherB<<<(NN * 32 + 255) / 256, 256>>>();
    k_gru<<<(NN + 127) / 128, 512, GRU_SMEM>>>(h_prev, W_ro, b_ro, h_next, out3);
}

// round 9
// speedup vs baseline: 1.5195x; 1.4064x over previous
#include <cuda_runtime.h>
#include <cstdint>

#define NN 100000
#define NH 20000
#define NE 800000
#define NE4 (NE/4)
#define NKA (NH*2)     // hedge-type keys
#define NKB (NN*2)     // node-type keys
#define NBA ((NKA + 1023) / 1024)
#define NBB ((NKB + 1023) / 1024)
#define NT  ((NN + 127) / 128)   // 782 GRU tiles
#define GRID_GRU 152

// ---------------- static device buffers ------------------------------------
__device__ __align__(16) float g_aggA[(size_t)2*NH*64];  // (Σx)/cnt per (t,h)
__device__ __align__(16) float g_efm[(size_t)2*NH*64];   // aggA @ Wcomb_t
__device__ __align__(16) float g_h[(size_t)NN*64];       // relu(mix)
__device__ int g_cntA[NKA], g_offA[NKA];
__device__ int g_cntB[NKB], g_offB[NKB];
__device__ int g_baseA, g_baseB;
__device__ __align__(16) int g_rankA[NE], g_rankB[NE];
__device__ int g_sortA[NE];   // node ids, sorted by (hedge,type)
__device__ int g_sortB[NE];   // efm row offsets (floats), sorted by (node,type)
// B images
__device__ __align__(16) float g_Bef[2*2*64*32];        // Wcomb_t (swizzled, tf32)
__device__ __align__(16) float g_Bgru[4*256*36];        // GRU B, pitch-36 raw tf32
__device__ float g_bias[256];
__device__ float g_bcmix[64];

// ---------------- helpers ---------------------------------------------------
__device__ __forceinline__ float to_tf32(float v) {
    uint32_t u; asm("cvt.rna.tf32.f32 %0, %1;" : "=r"(u) : "f"(v));
    return __uint_as_float(u);
}
__device__ __forceinline__ int swz(int kk, int row) {
    int r = kk & 7;
    int pos = (r < 4) ? (r * 2) : ((r - 4) * 2 + 1);
    int sc = (kk & 24) + pos;
    return (sc + ((row & 3) << 3)) & 31;
}
__device__ __forceinline__ void mma_tf32(float* c, const uint32_t* a,
                                         uint32_t b0, uint32_t b1) {
    asm volatile(
        "mma.sync.aligned.m16n8k8.row.col.f32.tf32.tf32.f32 "
        "{%0,%1,%2,%3}, {%4,%5,%6,%7}, {%8,%9}, {%0,%1,%2,%3};"
        : "+f"(c[0]), "+f"(c[1]), "+f"(c[2]), "+f"(c[3])
        : "r"(a[0]), "r"(a[1]), "r"(a[2]), "r"(a[3]), "r"(b0), "r"(b1));
}
__device__ __forceinline__ float sigf(float x) { return 1.f / (1.f + __expf(-x)); }
__device__ __forceinline__ float tanh_fast(float x) {
    return 1.f - 2.f / (__expf(2.f * x) + 1.f);
}
__device__ __forceinline__ void cp16(uint32_t dst, const void* src) {
    asm volatile("cp.async.cg.shared.global [%0], [%1], 16;" :: "r"(dst), "l"(src));
}
#define CP_COMMIT() asm volatile("cp.async.commit_group;" ::: "memory")
#define CP_WAIT0()  asm volatile("cp.async.wait_group 0;" ::: "memory")

// ---------------- prep (+ counter zeroing, merged) ---------------------------
__global__ void k_prep(const float* __restrict__ Wc, const float* __restrict__ Wmix,
                       const float* __restrict__ bmix, const float* __restrict__ bconv,
                       const float* __restrict__ Wih, const float* __restrict__ Whh,
                       const float* __restrict__ bih, const float* __restrict__ bhh) {
    int idx = blockIdx.x * blockDim.x + threadIdx.x;
    if (idx < NKA) g_cntA[idx] = 0;
    if (idx < NKB) g_cntB[idx] = 0;
    if (idx == 0) { g_baseA = 0; g_baseB = 0; }

    if (idx < 8192) {                     // Bef: [2][2 kc][64 c][32] (swizzled)
        int t = idx >> 12, rem = idx & 4095;
        int kc = rem >> 11, rem2 = rem & 2047, c = rem2 >> 5, kk = rem2 & 31;
        int k = kc * 32 + kk;
        float s = 0.f;
        const float* wr = Wc + t * 4096 + k * 64;
        const float* wm = Wmix + (size_t)t * 64 * 64 + c;
#pragma unroll 8
        for (int m = 0; m < 64; m++) s += wr[m] * wm[(size_t)m * 64];
        g_Bef[((t * 2 + kc) * 64 + c) * 32 + swz(kk, c)] = to_tf32(s);
    } else if (idx < 8192 + 36864) {      // Bgru: [4 kc][256 c][36], c = j*4+seg
        int i = idx - 8192;
        int kc = i / 9216, rem = i - kc * 9216;
        int c = rem / 36, kk = rem - c * 36;
        float v = 0.f;
        if (kk < 32) {
            int k = kc * 32 + kk;
            int j = c >> 2, seg = c & 3;
            if (k < 64) {
                if (seg == 0)      v = Wih[k * 192 + j];
                else if (seg == 1) v = Wih[k * 192 + 64 + j];
                else if (seg == 2) v = Wih[k * 192 + 128 + j];
            } else {
                int k2 = k - 64;
                if (seg == 0)      v = Whh[k2 * 192 + j];
                else if (seg == 1) v = Whh[k2 * 192 + 64 + j];
                else if (seg == 3) v = Whh[k2 * 192 + 128 + j];
            }
        }
        g_Bgru[i] = to_tf32(v);
    } else if (idx < 45056 + 256) {       // GRU bias (seg-major)
        int c = idx - 45056;
        int seg = c >> 6, j = c & 63;
        float b;
        if (seg == 0)      b = bih[j] + bhh[j];
        else if (seg == 1) b = bih[64 + j] + bhh[64 + j];
        else if (seg == 2) b = bih[128 + j];
        else               b = bhh[128 + j];
        g_bias[c] = b;
    } else if (idx < 45056 + 256 + 64) {  // folded mix bias
        int j = idx - 45056 - 256;
        float s = bmix[j];
        for (int k = 0; k < 128; k++) s += bconv[k] * Wmix[k * 64 + j];
        g_bcmix[j] = s;
    }
}

// ---------------- histogram + rank capture (int4, 4 edges/thread) -----------
__global__ void k_hist(const int* __restrict__ ni, const int* __restrict__ hi,
                       const int* __restrict__ ea) {
    int i = blockIdx.x * 256 + threadIdx.x;
    if (i >= NE4) return;
    int4 n = ((const int4*)ni)[i];
    int4 h = ((const int4*)hi)[i];
    int4 t = ((const int4*)ea)[i];
    int4 ra, rb;
    ra.x = atomicAdd(&g_cntA[h.x * 2 + t.x], 1);
    ra.y = atomicAdd(&g_cntA[h.y * 2 + t.y], 1);
    ra.z = atomicAdd(&g_cntA[h.z * 2 + t.z], 1);
    ra.w = atomicAdd(&g_cntA[h.w * 2 + t.w], 1);
    rb.x = atomicAdd(&g_cntB[n.x * 2 + t.x], 1);
    rb.y = atomicAdd(&g_cntB[n.y * 2 + t.y], 1);
    rb.z = atomicAdd(&g_cntB[n.z * 2 + t.z], 1);
    rb.w = atomicAdd(&g_cntB[n.w * 2 + t.w], 1);
    ((int4*)g_rankA)[i] = ra;
    ((int4*)g_rankB)[i] = rb;
}

// ---------------- parallel offsets: block scan + atomic range claim ---------
__global__ __launch_bounds__(1024) void k_offsets() {
    __shared__ int sm[1024];
    __shared__ int blockBase;
    int b = blockIdx.x;
    const int* cnt; int* off; int n; int* gbase;
    if (b < NBA) { cnt = g_cntA; off = g_offA; n = NKA; gbase = &g_baseA; }
    else { b -= NBA; cnt = g_cntB; off = g_offB; n = NKB; gbase = &g_baseB; }
    int tid = threadIdx.x;
    int i = b * 1024 + tid;
    int v = (i < n) ? cnt[i] : 0;
    sm[tid] = v;
    __syncthreads();
    for (int d = 1; d < 1024; d <<= 1) {
        int t = (tid >= d) ? sm[tid - d] : 0;
        __syncthreads();
        sm[tid] += t;
        __syncthreads();
    }
    if (tid == 1023) blockBase = atomicAdd(gbase, sm[1023]);
    __syncthreads();
    if (i < n) off[i] = blockBase + sm[tid] - v;
}

// ---------------- permute: atomic-free scatter using captured ranks ---------
__global__ void k_perm(const int* __restrict__ ni, const int* __restrict__ hi,
                       const int* __restrict__ ea) {
    int i = blockIdx.x * 256 + threadIdx.x;
    if (i >= NE4) return;
    int4 n = ((const int4*)ni)[i];
    int4 h = ((const int4*)hi)[i];
    int4 t = ((const int4*)ea)[i];
    int4 ra = ((const int4*)g_rankA)[i];
    int4 rb = ((const int4*)g_rankB)[i];
    g_sortA[g_offA[h.x * 2 + t.x] + ra.x] = n.x;
    g_sortA[g_offA[h.y * 2 + t.y] + ra.y] = n.y;
    g_sortA[g_offA[h.z * 2 + t.z] + ra.z] = n.z;
    g_sortA[g_offA[h.w * 2 + t.w] + ra.w] = n.w;
    g_sortB[g_offB[n.x * 2 + t.x] + rb.x] = (t.x * NH + h.x) * 64;
    g_sortB[g_offB[n.y * 2 + t.y] + rb.y] = (t.y * NH + h.y) * 64;
    g_sortB[g_offB[n.z * 2 + t.z] + rb.z] = (t.z * NH + h.z) * 64;
    g_sortB[g_offB[n.w * 2 + t.w] + rb.w] = (t.w * NH + h.w) * 64;
}

// ---------------- gather A: aggA[t,h] = (1/cnt) * sum x[node] ----------------
__global__ __launch_bounds__(256) void k_gatherA(const float* __restrict__ x) {
    int key = (blockIdx.x * 256 + threadIdx.x) >> 5;
    if (key >= NKA) return;
    int lane = threadIdx.x & 31;
    int t = key & 1, h = key >> 1;
    int base = g_offA[key], cnt = g_cntA[key];
    const float* xb = x + lane * 2;
    float ax = 0.f, ay = 0.f;
    int i = 0;
    for (; i + 8 <= cnt; i += 8) {
        float2 v[8];
#pragma unroll
        for (int q = 0; q < 8; q++) {
            int n = g_sortA[base + i + q];
            v[q] = *(const float2*)(xb + (size_t)n * 64);
        }
#pragma unroll
        for (int q = 0; q < 8; q++) { ax += v[q].x; ay += v[q].y; }
    }
    for (; i < cnt; i++) {
        int n = g_sortA[base + i];
        float2 v = *(const float2*)(xb + (size_t)n * 64);
        ax += v.x; ay += v.y;
    }
    float s = (cnt > 0) ? 1.f / (float)cnt : 0.f;
    *(float2*)&g_aggA[((size_t)t * NH + h) * 64 + lane * 2] = make_float2(ax * s, ay * s);
}

// ---------------- GEMM: efm = aggA @ Wcomb_t   (M=NH per type, N=64, K=64) --
__global__ __launch_bounds__(256) void k_mma_ef() {
    __shared__ __align__(16) float As[128][32];
    __shared__ __align__(16) float Bs[64][32];
    int tid = threadIdx.x;
    int lane = tid & 31, warp = tid >> 5;
    int warpM = warp >> 1, warpN = warp & 1;
    int g = lane >> 2, t4 = lane & 3;
    int rot = (g & 3) << 3;
    int n0 = blockIdx.x * 128;
    int ty = blockIdx.y;
    float acc[2][4][4] = {};
    for (int kc = 0; kc < 2; kc++) {
        __syncthreads();
        for (int i = tid; i < 4096; i += 256) {
            int m = i >> 5, kk = i & 31;
            int n = n0 + m;
            float v = (n < NH) ? g_aggA[((size_t)ty * NH + n) * 64 + kc * 32 + kk] : 0.f;
            As[m][swz(kk, m)] = to_tf32(v);
        }
        const float4* src = (const float4*)&g_Bef[(ty * 2 + kc) * 2048];
        float4* dst = (float4*)&Bs[0][0];
        for (int i = tid; i < 512; i += 256) dst[i] = src[i];
        __syncthreads();
#pragma unroll
        for (int s = 0; s < 4; s++) {
            int pc = (s * 8 + 2 * t4 + rot) & 31;
            uint32_t a[2][4];
#pragma unroll
            for (int mt = 0; mt < 2; mt++) {
                int r = warpM * 32 + mt * 16 + g;
                float2 lo = *(const float2*)&As[r][pc];
                float2 hi = *(const float2*)&As[r + 8][pc];
                a[mt][0] = __float_as_uint(lo.x); a[mt][1] = __float_as_uint(hi.x);
                a[mt][2] = __float_as_uint(lo.y); a[mt][3] = __float_as_uint(hi.y);
            }
#pragma unroll
            for (int nt = 0; nt < 4; nt++) {
                int c = warpN * 32 + nt * 8 + g;
                float2 b = *(const float2*)&Bs[c][pc];
                uint32_t b0 = __float_as_uint(b.x), b1 = __float_as_uint(b.y);
                mma_tf32(acc[0][nt], a[0], b0, b1);
                mma_tf32(acc[1][nt], a[1], b0, b1);
            }
        }
    }
#pragma unroll
    for (int mt = 0; mt < 2; mt++) {
        int r = n0 + warpM * 32 + mt * 16 + g;
#pragma unroll
        for (int nt = 0; nt < 4; nt++) {
            int c = warpN * 32 + nt * 8 + 2 * t4;
            if (r < NH)
                *(float2*)&g_efm[((size_t)ty * NH + r) * 64 + c] =
                    make_float2(acc[mt][nt][0], acc[mt][nt][1]);
            if (r + 8 < NH)
                *(float2*)&g_efm[((size_t)ty * NH + r + 8) * 64 + c] =
                    make_float2(acc[mt][nt][2], acc[mt][nt][3]);
        }
    }
}

// ---------------- gather B: h[n] = relu(sum_t Dinv_t * sum efm + bcmix) -----
__global__ __launch_bounds__(256) void k_gatherB() {
    int node = (blockIdx.x * 256 + threadIdx.x) >> 5;
    if (node >= NN) return;
    int lane = threadIdx.x & 31;
    const float* eb = g_efm + lane * 2;
    float ax = 0.f, ay = 0.f;
#pragma unroll
    for (int t = 0; t < 2; t++) {
        int key = node * 2 + t;
        int base = g_offB[key], cnt = g_cntB[key];
        float sx = 0.f, sy = 0.f;
        int i = 0;
        for (; i + 8 <= cnt; i += 8) {
            float2 v[8];
#pragma unroll
            for (int q = 0; q < 8; q++) {
                int o = g_sortB[base + i + q];
                v[q] = *(const float2*)(eb + o);
            }
#pragma unroll
            for (int q = 0; q < 8; q++) { sx += v[q].x; sy += v[q].y; }
        }
        for (; i < cnt; i++) {
            int o = g_sortB[base + i];
            float2 v = *(const float2*)(eb + o);
            sx += v.x; sy += v.y;
        }
        float s = (cnt > 0) ? 1.f / (float)cnt : 0.f;
        ax += sx * s; ay += sy * s;
    }
    float b0 = g_bcmix[lane * 2], b1 = g_bcmix[lane * 2 + 1];
    *(float2*)&g_h[(size_t)node * 64 + lane * 2] =
        make_float2(fmaxf(ax + b0, 0.f), fmaxf(ay + b1, 0.f));
}

// ---------------- persistent GRU: B-resident + cp.async pipelined A ---------
// smem floats: Ball[4][256][36]=36864 | As[2][128][36]=9216 | Wro3 256 | sred 512
#define OF_AS   36864
#define OF_WRO  46080
#define OF_SRED 46336
#define GRU_SMEM ((46848) * 4)
__global__ __launch_bounds__(512) void k_gru(const float* __restrict__ h_prev,
                                             const float* __restrict__ Wro,
                                             const float* __restrict__ bro,
                                             float* __restrict__ out_h,
                                             float* __restrict__ out3) {
    extern __shared__ __align__(16) float sm[];
    uint32_t smb;
    asm("{ .reg .u64 t; cvta.to.shared.u64 t, %1; cvt.u32.u64 %0, t; }"
        : "=r"(smb) : "l"(sm));
    int tid = threadIdx.x;
    int lane = tid & 31, warp = tid >> 5;
    int warpM = warp >> 2, warpN = warp & 3;
    int g = lane >> 2, t = lane & 3;

    // load all of B (147456 B = 9216 x 16B) — once per CTA
    for (int i = tid; i < 9216; i += 512)
        cp16(smb + (uint32_t)i * 16, (const char*)g_Bgru + (size_t)i * 16);
    CP_COMMIT();

    // Wro3 + sred init
    if (tid < 256) {
        int j = tid >> 2, c = tid & 3;
        sm[OF_WRO + tid] = (c < 3) ? __ldg(&Wro[j * 64 + c]) : 0.f;
    }
    sm[OF_SRED + tid] = 0.f;
    float brd0 = __ldg(&bro[0]), brd1 = __ldg(&bro[1]), brd2 = __ldg(&bro[2]);

    // stage issue lambda-ish macro: stage (tile, kc) into buffer kc&1
#define STAGE_A(ptile, pkc) do {                                               \
        int _kc = (pkc);                                                       \
        uint32_t _dst = smb + (OF_AS + (_kc & 1) * 4608) * 4;                  \
        for (int i = tid; i < 1024; i += 512) {                                \
            int m = i >> 3, q = i & 7;                                         \
            int n = (ptile) * 128 + m;                                         \
            int nc = (n < NN) ? n : (NN - 1);                                  \
            const float* src = (_kc < 2)                                       \
                ? &g_h[(size_t)nc * 64 + _kc * 32 + q * 4]                     \
                : &h_prev[(size_t)nc * 64 + (_kc - 2) * 32 + q * 4];           \
            cp16(_dst + (uint32_t)(m * 144 + q * 16), src);                    \
        }                                                                      \
    } while (0)

    int tile = blockIdx.x;
    if (tile < NT) STAGE_A(tile, 0);
    CP_COMMIT();

    for (; tile < NT; tile += GRID_GRU) {
        int n0 = tile * 128;
        float acc[2][8][4] = {};
        for (int kc = 0; kc < 4; kc++) {
            CP_WAIT0();
            __syncthreads();
            // issue next stage (same tile kc+1, or next tile kc0)
            {
                int nk = kc + 1, pt = tile;
                if (nk == 4) { nk = 0; pt = tile + GRID_GRU; }
                if (pt < NT) STAGE_A(pt, nk);
                CP_COMMIT();
            }
            // compute on buffer kc&1 against resident B chunk kc
            const float* As = sm + OF_AS + (kc & 1) * 4608;
            const float* Bb = sm + kc * 9216;
#pragma unroll
            for (int s = 0; s < 4; s++) {
                int k0 = s * 8;
                uint32_t a[2][4];
#pragma unroll
                for (int mt = 0; mt < 2; mt++) {
                    int r = warpM * 32 + mt * 16 + g;
                    a[mt][0] = __float_as_uint(As[r * 36 + k0 + t]);
                    a[mt][1] = __float_as_uint(As[(r + 8) * 36 + k0 + t]);
                    a[mt][2] = __float_as_uint(As[r * 36 + k0 + t + 4]);
                    a[mt][3] = __float_as_uint(As[(r + 8) * 36 + k0 + t + 4]);
                }
#pragma unroll
                for (int nt = 0; nt < 8; nt++) {
                    int c = warpN * 64 + nt * 8 + g;
                    uint32_t b0 = __float_as_uint(Bb[c * 36 + k0 + t]);
                    uint32_t b1 = __float_as_uint(Bb[c * 36 + k0 + t + 4]);
                    mma_tf32(acc[0][nt], a[0], b0, b1);
                    mma_tf32(acc[1][nt], a[1], b0, b1);
                }
            }
        }

        // ---- gate epilogue + fused readout partials ----
        float p[2][2][3] = {};
        bool even = (t & 1) == 0;
#pragma unroll
        for (int mt = 0; mt < 2; mt++) {
#pragma unroll
            for (int nt = 0; nt < 8; nt++) {
                int j = warpN * 16 + nt * 2 + (t >> 1);
                float br = g_bias[j], bz = g_bias[64 + j];
                float bn = g_bias[128 + j], bh = g_bias[192 + j];
                float w0 = sm[OF_WRO + j * 4 + 0];
                float w1 = sm[OF_WRO + j * 4 + 1];
                float w2 = sm[OF_WRO + j * 4 + 2];
#pragma unroll
                for (int rh = 0; rh < 2; rh++) {
                    int n = n0 + warpM * 32 + mt * 16 + rh * 8 + g;
                    float v0 = acc[mt][nt][rh * 2 + 0];
                    float v1 = acc[mt][nt][rh * 2 + 1];
                    float o0 = __shfl_xor_sync(0xffffffffu, v0, 1);
                    float o1 = __shfl_xor_sync(0xffffffffu, v1, 1);
                    float hn = 0.f;
                    if (even && n < NN) {
                        float r_ = sigf(v0 + br);
                        float z_ = sigf(v1 + bz);
                        float nv = tanh_fast((o0 + bn) + r_ * (o1 + bh));
                        float hp = h_prev[(size_t)n * 64 + j];
                        hn = (1.f - z_) * nv + z_ * hp;
                        out_h[(size_t)n * 64 + j] = hn;
                    }
                    p[mt][rh][0] += hn * w0;
                    p[mt][rh][1] += hn * w1;
                    p[mt][rh][2] += hn * w2;
                }
            }
        }
#pragma unroll
        for (int mt = 0; mt < 2; mt++)
#pragma unroll
            for (int rh = 0; rh < 2; rh++)
#pragma unroll
                for (int c = 0; c < 3; c++) {
                    float v = p[mt][rh][c] + __shfl_xor_sync(0xffffffffu, p[mt][rh][c], 2);
                    if (t == 0)
                        atomicAdd(&sm[OF_SRED + (warpM * 32 + mt * 16 + rh * 8 + g) * 4 + c], v);
                }
        __syncthreads();
        {
            int nd = tid >> 2, c = tid & 3;
            int n = n0 + nd;
            if (c < 3 && n < NN)
                out3[(size_t)n * 3 + c] = sm[OF_SRED + tid] +
                                          (c == 0 ? brd0 : (c == 1 ? brd1 : brd2));
        }
        __syncthreads();
        sm[OF_SRED + tid] = 0.f;   // reset for next tile (synced by kc-loop barriers)
    }
#undef STAGE_A
}

// ---------------- launch -----------------------------------------------------
extern "C" void kernel_launch(void* const* d_in, const int* in_sizes, int n_in,
                              void* d_out, int out_size) {
    const float* x       = (const float*)d_in[0];
    const float* h_prev  = (const float*)d_in[1];
    const int* node_idx  = (const int*)d_in[2];
    const int* hedge_idx = (const int*)d_in[3];
    const int* edge_attr = (const int*)d_in[4];
    const float* W_conv  = (const float*)d_in[5];
    const float* b_conv  = (const float*)d_in[6];
    const float* W_mix   = (const float*)d_in[7];
    const float* b_mix   = (const float*)d_in[8];
    const float* W_ih    = (const float*)d_in[9];
    const float* W_hh    = (const float*)d_in[10];
    const float* b_ih    = (const float*)d_in[11];
    const float* b_hh    = (const float*)d_in[12];
    const float* W_ro    = (const float*)d_in[13];
    const float* b_ro    = (const float*)d_in[14];

    float* h_next = (float*)d_out;
    float* out3   = (float*)d_out + (size_t)NN * 64;

    cudaFuncSetAttribute(k_gru, cudaFuncAttributeMaxDynamicSharedMemorySize, GRU_SMEM);

    k_prep<<<(NKB + 255) / 256, 256>>>(W_conv, W_mix, b_mix, b_conv,
                                       W_ih, W_hh, b_ih, b_hh);
    k_hist<<<(NE4 + 255) / 256, 256>>>(node_idx, hedge_idx, edge_attr);
    k_offsets<<<NBA + NBB, 1024>>>();
    k_perm<<<(NE4 + 255) / 256, 256>>>(node_idx, hedge_idx, edge_attr);
    k_gatherA<<<(NKA * 32 + 255) / 256, 256>>>(x);
    k_mma_ef<<<dim3((NH + 127) / 128, 2), 256>>>();
    k_gatherB<<<(NN * 32 + 255) / 256, 256>>>();
    k_gru<<<GRID_GRU, 512, GRU_SMEM>>>(h_prev, W_ro, b_ro, h_next, out3);
}

// round 10
// speedup vs baseline: 1.5216x; 1.0014x over previous
#include <cuda_runtime.h>
#include <cstdint>

#define NN 100000
#define NH 20000
#define NE 800000
#define NE4 (NE/4)
#define NE8 (NE/8)
#define NKA (NH*2)     // hedge-type keys
#define NKB (NN*2)     // node-type keys
#define NBA ((NKA + 1023) / 1024)
#define NBB ((NKB + 1023) / 1024)
#define NT  ((NN + 127) / 128)   // 782 GRU tiles
#define GRID_GRU 152

// ---------------- static device buffers ------------------------------------
__device__ __align__(16) float g_aggA[(size_t)2*NH*64];  // (Σx)/cnt per (t,h)
__device__ __align__(16) float g_efm[(size_t)2*NH*64];   // aggA @ Wcomb_t
__device__ __align__(16) float g_h[(size_t)NN*64];       // relu(mix)
__device__ int g_cntA[NKA], g_offA[NKA];
__device__ int g_cntB[NKB], g_offB[NKB];
__device__ int g_baseA, g_baseB;
__device__ __align__(16) int g_rankA[NE], g_rankB[NE];
__device__ int g_sortA[NE];   // node ids, sorted by (hedge,type)
__device__ int g_sortB[NE];   // efm row offsets (floats), sorted by (node,type)
// B images
__device__ __align__(16) float g_Bef[2*2*64*32];        // Wcomb_t (swizzled, tf32)
__device__ __align__(16) float g_Bgru[4*256*36];        // GRU B, pitch-36, pair-permuted k
__device__ float g_bias[256];
__device__ float g_bcmix[64];

// ---------------- helpers ---------------------------------------------------
__device__ __forceinline__ float to_tf32(float v) {
    uint32_t u; asm("cvt.rna.tf32.f32 %0, %1;" : "=r"(u) : "f"(v));
    return __uint_as_float(u);
}
__device__ __forceinline__ int swz(int kk, int row) {
    int r = kk & 7;
    int pos = (r < 4) ? (r * 2) : ((r - 4) * 2 + 1);
    int sc = (kk & 24) + pos;
    return (sc + ((row & 3) << 3)) & 31;
}
__device__ __forceinline__ void mma_tf32(float* c, const uint32_t* a,
                                         uint32_t b0, uint32_t b1) {
    asm volatile(
        "mma.sync.aligned.m16n8k8.row.col.f32.tf32.tf32.f32 "
        "{%0,%1,%2,%3}, {%4,%5,%6,%7}, {%8,%9}, {%0,%1,%2,%3};"
        : "+f"(c[0]), "+f"(c[1]), "+f"(c[2]), "+f"(c[3])
        : "r"(a[0]), "r"(a[1]), "r"(a[2]), "r"(a[3]), "r"(b0), "r"(b1));
}
__device__ __forceinline__ float sigf(float x) { return 1.f / (1.f + __expf(-x)); }
__device__ __forceinline__ float tanh_fast(float x) {
    return 1.f - 2.f / (__expf(2.f * x) + 1.f);
}
__device__ __forceinline__ void cp16(uint32_t dst, const void* src) {
    asm volatile("cp.async.cg.shared.global [%0], [%1], 16;" :: "r"(dst), "l"(src));
}
#define CP_COMMIT() asm volatile("cp.async.commit_group;" ::: "memory")
#define CP_WAIT0()  asm volatile("cp.async.wait_group 0;" ::: "memory")

// ---------------- merged prep + histogram -----------------------------------
// prep branches (idx-partitioned) are independent of the hist work; hist uses
// idx < NE4 (=200000) which the same grid covers.
__global__ void k_prep_hist(const float* __restrict__ Wc, const float* __restrict__ Wmix,
                            const float* __restrict__ bmix, const float* __restrict__ bconv,
                            const float* __restrict__ Wih, const float* __restrict__ Whh,
                            const float* __restrict__ bih, const float* __restrict__ bhh,
                            const int* __restrict__ ni, const int* __restrict__ hi,
                            const int* __restrict__ ea) {
    int idx = blockIdx.x * blockDim.x + threadIdx.x;
    if (idx == 0) { g_baseA = 0; g_baseB = 0; }

    // ---- prep (low idx only) ----
    if (idx < 8192) {                     // Bef: [2][2 kc][64 c][32] (swizzled)
        int t = idx >> 12, rem = idx & 4095;
        int kc = rem >> 11, rem2 = rem & 2047, c = rem2 >> 5, kk = rem2 & 31;
        int k = kc * 32 + kk;
        float s = 0.f;
        const float* wr = Wc + t * 4096 + k * 64;
        const float* wm = Wmix + (size_t)t * 64 * 64 + c;
#pragma unroll 8
        for (int m = 0; m < 64; m++) s += wr[m] * wm[(size_t)m * 64];
        g_Bef[((t * 2 + kc) * 64 + c) * 32 + swz(kk, c)] = to_tf32(s);
    } else if (idx < 8192 + 36864) {      // Bgru: [4 kc][256 c][36], pair-permuted k
        int i = idx - 8192;
        int kc = i / 9216, rem = i - kc * 9216;
        int c = rem / 36, kkp = rem - c * 36;
        float v = 0.f;
        if (kkp < 32) {
            // inverse pair permutation: storage kkp -> source kk
            int k0 = kkp & ~7, r = kkp & 7;
            int kk = k0 + (r >> 1) + ((r & 1) ? 4 : 0);
            int k = kc * 32 + kk;
            int j = c >> 2, seg = c & 3;
            if (k < 64) {
                if (seg == 0)      v = Wih[k * 192 + j];
                else if (seg == 1) v = Wih[k * 192 + 64 + j];
                else if (seg == 2) v = Wih[k * 192 + 128 + j];
            } else {
                int k2 = k - 64;
                if (seg == 0)      v = Whh[k2 * 192 + j];
                else if (seg == 1) v = Whh[k2 * 192 + 64 + j];
                else if (seg == 3) v = Whh[k2 * 192 + 128 + j];
            }
        }
        g_Bgru[i] = to_tf32(v);
    } else if (idx < 45056 + 256) {       // GRU bias (seg-major)
        int c = idx - 45056;
        int seg = c >> 6, j = c & 63;
        float b;
        if (seg == 0)      b = bih[j] + bhh[j];
        else if (seg == 1) b = bih[64 + j] + bhh[64 + j];
        else if (seg == 2) b = bih[128 + j];
        else               b = bhh[128 + j];
        g_bias[c] = b;
    } else if (idx < 45056 + 256 + 64) {  // folded mix bias
        int j = idx - 45056 - 256;
        float s = bmix[j];
        for (int k = 0; k < 128; k++) s += bconv[k] * Wmix[k * 64 + j];
        g_bcmix[j] = s;
    }

    // ---- histogram + rank capture (4 edges/thread) ----
    if (idx < NE4) {
        int4 n = ((const int4*)ni)[idx];
        int4 h = ((const int4*)hi)[idx];
        int4 t = ((const int4*)ea)[idx];
        int4 ra, rb;
        ra.x = atomicAdd(&g_cntA[h.x * 2 + t.x], 1);
        ra.y = atomicAdd(&g_cntA[h.y * 2 + t.y], 1);
        ra.z = atomicAdd(&g_cntA[h.z * 2 + t.z], 1);
        ra.w = atomicAdd(&g_cntA[h.w * 2 + t.w], 1);
        rb.x = atomicAdd(&g_cntB[n.x * 2 + t.x], 1);
        rb.y = atomicAdd(&g_cntB[n.y * 2 + t.y], 1);
        rb.z = atomicAdd(&g_cntB[n.z * 2 + t.z], 1);
        rb.w = atomicAdd(&g_cntB[n.w * 2 + t.w], 1);
        ((int4*)g_rankA)[idx] = ra;
        ((int4*)g_rankB)[idx] = rb;
    }
}

// ---------------- zero counters (runs before prep_hist) ---------------------
__global__ void k_zero_cnt() {
    int i = blockIdx.x * 256 + threadIdx.x;
    if (i < NKA) g_cntA[i] = 0;
    if (i < NKB) g_cntB[i] = 0;
}

// ---------------- parallel offsets: block scan + atomic range claim ---------
__global__ __launch_bounds__(1024) void k_offsets() {
    __shared__ int sm[1024];
    __shared__ int blockBase;
    int b = blockIdx.x;
    const int* cnt; int* off; int n; int* gbase;
    if (b < NBA) { cnt = g_cntA; off = g_offA; n = NKA; gbase = &g_baseA; }
    else { b -= NBA; cnt = g_cntB; off = g_offB; n = NKB; gbase = &g_baseB; }
    int tid = threadIdx.x;
    int i = b * 1024 + tid;
    int v = (i < n) ? cnt[i] : 0;
    sm[tid] = v;
    __syncthreads();
    for (int d = 1; d < 1024; d <<= 1) {
        int t = (tid >= d) ? sm[tid - d] : 0;
        __syncthreads();
        sm[tid] += t;
        __syncthreads();
    }
    if (tid == 1023) blockBase = atomicAdd(gbase, sm[1023]);
    __syncthreads();
    if (i < n) off[i] = blockBase + sm[tid] - v;
}

// ---------------- permute: atomic-free scatter, 8 edges/thread --------------
__global__ void k_perm(const int* __restrict__ ni, const int* __restrict__ hi,
                       const int* __restrict__ ea) {
    int i = blockIdx.x * 256 + threadIdx.x;
    if (i >= NE8) return;
#pragma unroll
    for (int half = 0; half < 2; half++) {
        int q = i * 2 + half;
        int4 n = ((const int4*)ni)[q];
        int4 h = ((const int4*)hi)[q];
        int4 t = ((const int4*)ea)[q];
        int4 ra = ((const int4*)g_rankA)[q];
        int4 rb = ((const int4*)g_rankB)[q];
        g_sortA[g_offA[h.x * 2 + t.x] + ra.x] = n.x;
        g_sortA[g_offA[h.y * 2 + t.y] + ra.y] = n.y;
        g_sortA[g_offA[h.z * 2 + t.z] + ra.z] = n.z;
        g_sortA[g_offA[h.w * 2 + t.w] + ra.w] = n.w;
        g_sortB[g_offB[n.x * 2 + t.x] + rb.x] = (t.x * NH + h.x) * 64;
        g_sortB[g_offB[n.y * 2 + t.y] + rb.y] = (t.y * NH + h.y) * 64;
        g_sortB[g_offB[n.z * 2 + t.z] + rb.z] = (t.z * NH + h.z) * 64;
        g_sortB[g_offB[n.w * 2 + t.w] + rb.w] = (t.w * NH + h.w) * 64;
    }
}

// ---------------- gather A: aggA[t,h] = (1/cnt) * sum x[node] ----------------
__global__ __launch_bounds__(256) void k_gatherA(const float* __restrict__ x) {
    int key = (blockIdx.x * 256 + threadIdx.x) >> 5;
    if (key >= NKA) return;
    int lane = threadIdx.x & 31;
    int t = key & 1, h = key >> 1;
    int base = g_offA[key], cnt = g_cntA[key];
    const float* xb = x + lane * 2;
    float ax = 0.f, ay = 0.f;
    int i = 0;
    for (; i + 8 <= cnt; i += 8) {
        float2 v[8];
#pragma unroll
        for (int q = 0; q < 8; q++) {
            int n = g_sortA[base + i + q];
            v[q] = *(const float2*)(xb + (size_t)n * 64);
        }
#pragma unroll
        for (int q = 0; q < 8; q++) { ax += v[q].x; ay += v[q].y; }
    }
    for (; i < cnt; i++) {
        int n = g_sortA[base + i];
        float2 v = *(const float2*)(xb + (size_t)n * 64);
        ax += v.x; ay += v.y;
    }
    float s = (cnt > 0) ? 1.f / (float)cnt : 0.f;
    *(float2*)&g_aggA[((size_t)t * NH + h) * 64 + lane * 2] = make_float2(ax * s, ay * s);
}

// ---------------- GEMM: efm = aggA @ Wcomb_t   (M=NH per type, N=64, K=64) --
__global__ __launch_bounds__(256) void k_mma_ef() {
    __shared__ __align__(16) float As[128][32];
    __shared__ __align__(16) float Bs[64][32];
    int tid = threadIdx.x;
    int lane = tid & 31, warp = tid >> 5;
    int warpM = warp >> 1, warpN = warp & 1;
    int g = lane >> 2, t4 = lane & 3;
    int rot = (g & 3) << 3;
    int n0 = blockIdx.x * 128;
    int ty = blockIdx.y;
    float acc[2][4][4] = {};
    for (int kc = 0; kc < 2; kc++) {
        __syncthreads();
        for (int i = tid; i < 4096; i += 256) {
            int m = i >> 5, kk = i & 31;
            int n = n0 + m;
            float v = (n < NH) ? g_aggA[((size_t)ty * NH + n) * 64 + kc * 32 + kk] : 0.f;
            As[m][swz(kk, m)] = to_tf32(v);
        }
        const float4* src = (const float4*)&g_Bef[(ty * 2 + kc) * 2048];
        float4* dst = (float4*)&Bs[0][0];
        for (int i = tid; i < 512; i += 256) dst[i] = src[i];
        __syncthreads();
#pragma unroll
        for (int s = 0; s < 4; s++) {
            int pc = (s * 8 + 2 * t4 + rot) & 31;
            uint32_t a[2][4];
#pragma unroll
            for (int mt = 0; mt < 2; mt++) {
                int r = warpM * 32 + mt * 16 + g;
                float2 lo = *(const float2*)&As[r][pc];
                float2 hi = *(const float2*)&As[r + 8][pc];
                a[mt][0] = __float_as_uint(lo.x); a[mt][1] = __float_as_uint(hi.x);
                a[mt][2] = __float_as_uint(lo.y); a[mt][3] = __float_as_uint(hi.y);
            }
#pragma unroll
            for (int nt = 0; nt < 4; nt++) {
                int c = warpN * 32 + nt * 8 + g;
                float2 b = *(const float2*)&Bs[c][pc];
                uint32_t b0 = __float_as_uint(b.x), b1 = __float_as_uint(b.y);
                mma_tf32(acc[0][nt], a[0], b0, b1);
                mma_tf32(acc[1][nt], a[1], b0, b1);
            }
        }
    }
#pragma unroll
    for (int mt = 0; mt < 2; mt++) {
        int r = n0 + warpM * 32 + mt * 16 + g;
#pragma unroll
        for (int nt = 0; nt < 4; nt++) {
            int c = warpN * 32 + nt * 8 + 2 * t4;
            if (r < NH)
                *(float2*)&g_efm[((size_t)ty * NH + r) * 64 + c] =
                    make_float2(acc[mt][nt][0], acc[mt][nt][1]);
            if (r + 8 < NH)
                *(float2*)&g_efm[((size_t)ty * NH + r + 8) * 64 + c] =
                    make_float2(acc[mt][nt][2], acc[mt][nt][3]);
        }
    }
}

// ---------------- gather B: h[n] = relu(sum_t Dinv_t * sum efm + bcmix) -----
__global__ __launch_bounds__(256) void k_gatherB() {
    int node = (blockIdx.x * 256 + threadIdx.x) >> 5;
    if (node >= NN) return;
    int lane = threadIdx.x & 31;
    const float* eb = g_efm + lane * 2;
    float ax = 0.f, ay = 0.f;
#pragma unroll
    for (int t = 0; t < 2; t++) {
        int key = node * 2 + t;
        int base = g_offB[key], cnt = g_cntB[key];
        float sx = 0.f, sy = 0.f;
        int i = 0;
        for (; i + 8 <= cnt; i += 8) {
            float2 v[8];
#pragma unroll
            for (int q = 0; q < 8; q++) {
                int o = g_sortB[base + i + q];
                v[q] = *(const float2*)(eb + o);
            }
#pragma unroll
            for (int q = 0; q < 8; q++) { sx += v[q].x; sy += v[q].y; }
        }
        for (; i < cnt; i++) {
            int o = g_sortB[base + i];
            float2 v = *(const float2*)(eb + o);
            sx += v.x; sy += v.y;
        }
        float s = (cnt > 0) ? 1.f / (float)cnt : 0.f;
        ax += sx * s; ay += sy * s;
    }
    float b0 = g_bcmix[lane * 2], b1 = g_bcmix[lane * 2 + 1];
    *(float2*)&g_h[(size_t)node * 64 + lane * 2] =
        make_float2(fmaxf(ax + b0, 0.f), fmaxf(ay + b1, 0.f));
}

// ---------------- persistent GRU: B-resident + cp.async pipelined A ---------
// smem floats: Ball[4][256][36]=36864 | As[2][128][36]=9216 | Wro3 256 | sred 512
#define OF_AS   36864
#define OF_WRO  46080
#define OF_SRED 46336
#define GRU_SMEM ((46848) * 4)
__global__ __launch_bounds__(512) void k_gru(const float* __restrict__ h_prev,
                                             const float* __restrict__ Wro,
                                             const float* __restrict__ bro,
                                             float* __restrict__ out_h,
                                             float* __restrict__ out3) {
    extern __shared__ __align__(16) float sm[];
    uint32_t smb;
    asm("{ .reg .u64 t; cvta.to.shared.u64 t, %1; cvt.u32.u64 %0, t; }"
        : "=r"(smb) : "l"(sm));
    int tid = threadIdx.x;
    int lane = tid & 31, warp = tid >> 5;
    int warpM = warp >> 2, warpN = warp & 3;
    int g = lane >> 2, t = lane & 3;

    // load all of B (147456 B = 9216 x 16B) — once per CTA
    for (int i = tid; i < 9216; i += 512)
        cp16(smb + (uint32_t)i * 16, (const char*)g_Bgru + (size_t)i * 16);
    CP_COMMIT();

    if (tid < 256) {
        int j = tid >> 2, c = tid & 3;
        sm[OF_WRO + tid] = (c < 3) ? __ldg(&Wro[j * 64 + c]) : 0.f;
    }
    sm[OF_SRED + tid] = 0.f;
    float brd0 = __ldg(&bro[0]), brd1 = __ldg(&bro[1]), brd2 = __ldg(&bro[2]);

#define STAGE_A(ptile, pkc) do {                                               \
        int _kc = (pkc);                                                       \
        uint32_t _dst = smb + (OF_AS + (_kc & 1) * 4608) * 4;                  \
        for (int i = tid; i < 1024; i += 512) {                                \
            int m = i >> 3, q = i & 7;                                         \
            int n = (ptile) * 128 + m;                                         \
            int nc = (n < NN) ? n : (NN - 1);                                  \
            const float* src = (_kc < 2)                                       \
                ? &g_h[(size_t)nc * 64 + _kc * 32 + q * 4]                     \
                : &h_prev[(size_t)nc * 64 + (_kc - 2) * 32 + q * 4];           \
            cp16(_dst + (uint32_t)(m * 144 + q * 16), src);                    \
        }                                                                      \
    } while (0)

    int tile = blockIdx.x;
    if (tile < NT) STAGE_A(tile, 0);
    CP_COMMIT();

    for (; tile < NT; tile += GRID_GRU) {
        int n0 = tile * 128;
        float acc[2][8][4] = {};
        for (int kc = 0; kc < 4; kc++) {
            CP_WAIT0();
            __syncthreads();
            {
                int nk = kc + 1, pt = tile;
                if (nk == 4) { nk = 0; pt = tile + GRID_GRU; }
                if (pt < NT) STAGE_A(pt, nk);
                CP_COMMIT();
            }
            const float* As = sm + OF_AS + (kc & 1) * 4608;
            const float* Bb = sm + kc * 9216;
#pragma unroll
            for (int s = 0; s < 4; s++) {
                int k0 = s * 8;
                uint32_t a[2][4];
#pragma unroll
                for (int mt = 0; mt < 2; mt++) {
                    int r = warpM * 32 + mt * 16 + g;
                    a[mt][0] = __float_as_uint(As[r * 36 + k0 + t]);
                    a[mt][1] = __float_as_uint(As[(r + 8) * 36 + k0 + t]);
                    a[mt][2] = __float_as_uint(As[r * 36 + k0 + t + 4]);
                    a[mt][3] = __float_as_uint(As[(r + 8) * 36 + k0 + t + 4]);
                }
#pragma unroll
                for (int nt = 0; nt < 8; nt++) {
                    int c = warpN * 64 + nt * 8 + g;
                    // pair-permuted B: (k0+t, k0+t+4) stored adjacent -> one LDS.64
                    float2 bb = *(const float2*)&Bb[c * 36 + k0 + 2 * t];
                    mma_tf32(acc[0][nt], a[0],
                             __float_as_uint(bb.x), __float_as_uint(bb.y));
                    mma_tf32(acc[1][nt], a[1],
                             __float_as_uint(bb.x), __float_as_uint(bb.y));
                }
            }
        }

        // ---- gate epilogue + fused readout partials ----
        float p[2][2][3] = {};
        bool even = (t & 1) == 0;
#pragma unroll
        for (int mt = 0; mt < 2; mt++) {
#pragma unroll
            for (int nt = 0; nt < 8; nt++) {
                int j = warpN * 16 + nt * 2 + (t >> 1);
                float br = g_bias[j], bz = g_bias[64 + j];
                float bn = g_bias[128 + j], bh = g_bias[192 + j];
                float w0 = sm[OF_WRO + j * 4 + 0];
                float w1 = sm[OF_WRO + j * 4 + 1];
                float w2 = sm[OF_WRO + j * 4 + 2];
#pragma unroll
                for (int rh = 0; rh < 2; rh++) {
                    int n = n0 + warpM * 32 + mt * 16 + rh * 8 + g;
                    float v0 = acc[mt][nt][rh * 2 + 0];
                    float v1 = acc[mt][nt][rh * 2 + 1];
                    float o0 = __shfl_xor_sync(0xffffffffu, v0, 1);
                    float o1 = __shfl_xor_sync(0xffffffffu, v1, 1);
                    float hn = 0.f;
                    if (even && n < NN) {
                        float r_ = sigf(v0 + br);
                        float z_ = sigf(v1 + bz);
                        float nv = tanh_fast((o0 + bn) + r_ * (o1 + bh));
                        float hp = h_prev[(size_t)n * 64 + j];
                        hn = (1.f - z_) * nv + z_ * hp;
                        out_h[(size_t)n * 64 + j] = hn;
                    }
                    p[mt][rh][0] += hn * w0;
                    p[mt][rh][1] += hn * w1;
                    p[mt][rh][2] += hn * w2;
                }
            }
        }
#pragma unroll
        for (int mt = 0; mt < 2; mt++)
#pragma unroll
            for (int rh = 0; rh < 2; rh++)
#pragma unroll
                for (int c = 0; c < 3; c++) {
                    float v = p[mt][rh][c] + __shfl_xor_sync(0xffffffffu, p[mt][rh][c], 2);
                    if (t == 0)
                        atomicAdd(&sm[OF_SRED + (warpM * 32 + mt * 16 + rh * 8 + g) * 4 + c], v);
                }
        __syncthreads();
        {
            int nd = tid >> 2, c = tid & 3;
            int n = n0 + nd;
            if (c < 3 && n < NN)
                out3[(size_t)n * 3 + c] = sm[OF_SRED + tid] +
                                          (c == 0 ? brd0 : (c == 1 ? brd1 : brd2));
        }
        __syncthreads();
        sm[OF_SRED + tid] = 0.f;
    }
#undef STAGE_A
}

// ---------------- launch -----------------------------------------------------
extern "C" void kernel_launch(void* const* d_in, const int* in_sizes, int n_in,
                              void* d_out, int out_size) {
    const float* x       = (const float*)d_in[0];
    const float* h_prev  = (const float*)d_in[1];
    const int* node_idx  = (const int*)d_in[2];
    const int* hedge_idx = (const int*)d_in[3];
    const int* edge_attr = (const int*)d_in[4];
    const float* W_conv  = (const float*)d_in[5];
    const float* b_conv  = (const float*)d_in[6];
    const float* W_mix   = (const float*)d_in[7];
    const float* b_mix   = (const float*)d_in[8];
    const float* W_ih    = (const float*)d_in[9];
    const float* W_hh    = (const float*)d_in[10];
    const float* b_ih    = (const float*)d_in[11];
    const float* b_hh    = (const float*)d_in[12];
    const float* W_ro    = (const float*)d_in[13];
    const float* b_ro    = (const float*)d_in[14];

    float* h_next = (float*)d_out;
    float* out3   = (float*)d_out + (size_t)NN * 64;

    cudaFuncSetAttribute(k_gru, cudaFuncAttributeMaxDynamicSharedMemorySize, GRU_SMEM);

    k_zero_cnt<<<(NKB + 255) / 256, 256>>>();
    k_prep_hist<<<(NE4 + 255) / 256, 256>>>(W_conv, W_mix, b_mix, b_conv,
                                            W_ih, W_hh, b_ih, b_hh,
                                            node_idx, hedge_idx, edge_attr);
    k_offsets<<<NBA + NBB, 1024>>>();
    k_perm<<<(NE8 + 255) / 256, 256>>>(node_idx, hedge_idx, edge_attr);
    k_gatherA<<<(NKA * 32 + 255) / 256, 256>>>(x);
    k_mma_ef<<<dim3((NH + 127) / 128, 2), 256>>>();
    k_gatherB<<<(NN * 32 + 255) / 256, 256>>>();
    k_gru<<<GRID_GRU, 512, GRU_SMEM>>>(h_prev, W_ro, b_ro, h_next, out3);
}

// round 11
// speedup vs baseline: 1.5617x; 1.0263x over previous
#include <cuda_runtime.h>
#include <cstdint>

#define NN 100000
#define NH 20000
#define NE 800000
#define NE4 (NE/4)
#define NKA (NH*2)     // hedge-type keys
#define NKB (NN*2)     // node-type keys
#define NBA ((NKA + 1023) / 1024)
#define NBB ((NKB + 1023) / 1024)
#define NT  ((NN + 127) / 128)   // 782 GRU tiles
#define GRID_GRU 152

// ---------------- static device buffers ------------------------------------
__device__ __align__(16) float g_aggA[(size_t)2*NH*64];  // (Σx)/cnt per (t,h)
__device__ __align__(16) float g_efm[(size_t)2*NH*64];   // aggA @ Wcomb_t
__device__ __align__(16) float g_h[(size_t)NN*64];       // relu(mix)
__device__ int g_cntA[NKA], g_offA[NKA];
__device__ int g_cntB[NKB], g_offB[NKB];
__device__ int g_baseA, g_baseB;
__device__ __align__(16) int g_rankA[NE], g_rankB[NE];
__device__ int g_sortA[NE];   // node ids, sorted by (hedge,type)
__device__ int g_sortB[NE];   // efm row offsets (floats), sorted by (node,type)
// B images
__device__ __align__(16) float g_Bef[2*2*64*32];        // Wcomb_t (swizzled, tf32)
__device__ __align__(16) float g_Bgru[4*256*36];        // GRU B, pitch-36, pair-permuted k
__device__ float g_bias[256];
__device__ float g_bcmix[64];

// ---------------- helpers ---------------------------------------------------
__device__ __forceinline__ float to_tf32(float v) {
    uint32_t u; asm("cvt.rna.tf32.f32 %0, %1;" : "=r"(u) : "f"(v));
    return __uint_as_float(u);
}
__device__ __forceinline__ int swz(int kk, int row) {
    int r = kk & 7;
    int pos = (r < 4) ? (r * 2) : ((r - 4) * 2 + 1);
    int sc = (kk & 24) + pos;
    return (sc + ((row & 3) << 3)) & 31;
}
__device__ __forceinline__ void mma_tf32(float* c, const uint32_t* a,
                                         uint32_t b0, uint32_t b1) {
    asm volatile(
        "mma.sync.aligned.m16n8k8.row.col.f32.tf32.tf32.f32 "
        "{%0,%1,%2,%3}, {%4,%5,%6,%7}, {%8,%9}, {%0,%1,%2,%3};"
        : "+f"(c[0]), "+f"(c[1]), "+f"(c[2]), "+f"(c[3])
        : "r"(a[0]), "r"(a[1]), "r"(a[2]), "r"(a[3]), "r"(b0), "r"(b1));
}
__device__ __forceinline__ float sigf(float x) { return 1.f / (1.f + __expf(-x)); }
__device__ __forceinline__ float tanh_fast(float x) {
    return 1.f - 2.f / (__expf(2.f * x) + 1.f);
}
__device__ __forceinline__ void cp16(uint32_t dst, const void* src) {
    asm volatile("cp.async.cg.shared.global [%0], [%1], 16;" :: "r"(dst), "l"(src));
}
#define CP_COMMIT() asm volatile("cp.async.commit_group;" ::: "memory")
#define CP_WAIT0()  asm volatile("cp.async.wait_group 0;" ::: "memory")

// ---------------- merged prep + histogram -----------------------------------
__global__ void k_prep_hist(const float* __restrict__ Wc, const float* __restrict__ Wmix,
                            const float* __restrict__ bmix, const float* __restrict__ bconv,
                            const float* __restrict__ Wih, const float* __restrict__ Whh,
                            const float* __restrict__ bih, const float* __restrict__ bhh,
                            const int* __restrict__ ni, const int* __restrict__ hi,
                            const int* __restrict__ ea) {
    int idx = blockIdx.x * blockDim.x + threadIdx.x;
    if (idx == 0) { g_baseA = 0; g_baseB = 0; }

    if (idx < 8192) {                     // Bef: [2][2 kc][64 c][32] (swizzled)
        int t = idx >> 12, rem = idx & 4095;
        int kc = rem >> 11, rem2 = rem & 2047, c = rem2 >> 5, kk = rem2 & 31;
        int k = kc * 32 + kk;
        float s = 0.f;
        const float* wr = Wc + t * 4096 + k * 64;
        const float* wm = Wmix + (size_t)t * 64 * 64 + c;
#pragma unroll 8
        for (int m = 0; m < 64; m++) s += wr[m] * wm[(size_t)m * 64];
        g_Bef[((t * 2 + kc) * 64 + c) * 32 + swz(kk, c)] = to_tf32(s);
    } else if (idx < 8192 + 36864) {      // Bgru: [4 kc][256 c][36], pair-permuted k
        int i = idx - 8192;
        int kc = i / 9216, rem = i - kc * 9216;
        int c = rem / 36, kkp = rem - c * 36;
        float v = 0.f;
        if (kkp < 32) {
            int k0 = kkp & ~7, r = kkp & 7;
            int kk = k0 + (r >> 1) + ((r & 1) ? 4 : 0);
            int k = kc * 32 + kk;
            int j = c >> 2, seg = c & 3;
            if (k < 64) {
                if (seg == 0)      v = Wih[k * 192 + j];
                else if (seg == 1) v = Wih[k * 192 + 64 + j];
                else if (seg == 2) v = Wih[k * 192 + 128 + j];
            } else {
                int k2 = k - 64;
                if (seg == 0)      v = Whh[k2 * 192 + j];
                else if (seg == 1) v = Whh[k2 * 192 + 64 + j];
                else if (seg == 3) v = Whh[k2 * 192 + 128 + j];
            }
        }
        g_Bgru[i] = to_tf32(v);
    } else if (idx < 45056 + 256) {       // GRU bias (seg-major)
        int c = idx - 45056;
        int seg = c >> 6, j = c & 63;
        float b;
        if (seg == 0)      b = bih[j] + bhh[j];
        else if (seg == 1) b = bih[64 + j] + bhh[64 + j];
        else if (seg == 2) b = bih[128 + j];
        else               b = bhh[128 + j];
        g_bias[c] = b;
    } else if (idx < 45056 + 256 + 64) {  // folded mix bias
        int j = idx - 45056 - 256;
        float s = bmix[j];
        for (int k = 0; k < 128; k++) s += bconv[k] * Wmix[k * 64 + j];
        g_bcmix[j] = s;
    }

    if (idx < NE4) {
        int4 n = ((const int4*)ni)[idx];
        int4 h = ((const int4*)hi)[idx];
        int4 t = ((const int4*)ea)[idx];
        int4 ra, rb;
        ra.x = atomicAdd(&g_cntA[h.x * 2 + t.x], 1);
        ra.y = atomicAdd(&g_cntA[h.y * 2 + t.y], 1);
        ra.z = atomicAdd(&g_cntA[h.z * 2 + t.z], 1);
        ra.w = atomicAdd(&g_cntA[h.w * 2 + t.w], 1);
        rb.x = atomicAdd(&g_cntB[n.x * 2 + t.x], 1);
        rb.y = atomicAdd(&g_cntB[n.y * 2 + t.y], 1);
        rb.z = atomicAdd(&g_cntB[n.z * 2 + t.z], 1);
        rb.w = atomicAdd(&g_cntB[n.w * 2 + t.w], 1);
        ((int4*)g_rankA)[idx] = ra;
        ((int4*)g_rankB)[idx] = rb;
    }
}

// ---------------- zero counters (runs before prep_hist) ---------------------
__global__ void k_zero_cnt() {
    int i = blockIdx.x * 256 + threadIdx.x;
    if (i < NKA) g_cntA[i] = 0;
    if (i < NKB) g_cntB[i] = 0;
}

// ---------------- parallel offsets: block scan + atomic range claim ---------
__global__ __launch_bounds__(1024) void k_offsets() {
    __shared__ int sm[1024];
    __shared__ int blockBase;
    int b = blockIdx.x;
    const int* cnt; int* off; int n; int* gbase;
    if (b < NBA) { cnt = g_cntA; off = g_offA; n = NKA; gbase = &g_baseA; }
    else { b -= NBA; cnt = g_cntB; off = g_offB; n = NKB; gbase = &g_baseB; }
    int tid = threadIdx.x;
    int i = b * 1024 + tid;
    int v = (i < n) ? cnt[i] : 0;
    sm[tid] = v;
    __syncthreads();
    for (int d = 1; d < 1024; d <<= 1) {
        int t = (tid >= d) ? sm[tid - d] : 0;
        __syncthreads();
        sm[tid] += t;
        __syncthreads();
    }
    if (tid == 1023) blockBase = atomicAdd(gbase, sm[1023]);
    __syncthreads();
    if (i < n) off[i] = blockBase + sm[tid] - v;
}

// ---------------- permute: atomic-free scatter, 4 edges/thread --------------
__global__ void k_perm(const int* __restrict__ ni, const int* __restrict__ hi,
                       const int* __restrict__ ea) {
    int i = blockIdx.x * 256 + threadIdx.x;
    if (i >= NE4) return;
    int4 n = ((const int4*)ni)[i];
    int4 h = ((const int4*)hi)[i];
    int4 t = ((const int4*)ea)[i];
    int4 ra = ((const int4*)g_rankA)[i];
    int4 rb = ((const int4*)g_rankB)[i];
    g_sortA[g_offA[h.x * 2 + t.x] + ra.x] = n.x;
    g_sortA[g_offA[h.y * 2 + t.y] + ra.y] = n.y;
    g_sortA[g_offA[h.z * 2 + t.z] + ra.z] = n.z;
    g_sortA[g_offA[h.w * 2 + t.w] + ra.w] = n.w;
    g_sortB[g_offB[n.x * 2 + t.x] + rb.x] = (t.x * NH + h.x) * 64;
    g_sortB[g_offB[n.y * 2 + t.y] + rb.y] = (t.y * NH + h.y) * 64;
    g_sortB[g_offB[n.z * 2 + t.z] + rb.z] = (t.z * NH + h.z) * 64;
    g_sortB[g_offB[n.w * 2 + t.w] + rb.w] = (t.w * NH + h.w) * 64;
}

// ---------------- gather A: aggA[t,h] = (1/cnt) * sum x[node] ----------------
__global__ __launch_bounds__(256) void k_gatherA(const float* __restrict__ x) {
    int key = (blockIdx.x * 256 + threadIdx.x) >> 5;
    if (key >= NKA) return;
    int lane = threadIdx.x & 31;
    int t = key & 1, h = key >> 1;
    int base = g_offA[key], cnt = g_cntA[key];
    const float* xb = x + lane * 2;
    float ax = 0.f, ay = 0.f;
    int i = 0;
    for (; i + 8 <= cnt; i += 8) {
        float2 v[8];
#pragma unroll
        for (int q = 0; q < 8; q++) {
            int n = g_sortA[base + i + q];
            v[q] = *(const float2*)(xb + (size_t)n * 64);
        }
#pragma unroll
        for (int q = 0; q < 8; q++) { ax += v[q].x; ay += v[q].y; }
    }
    for (; i < cnt; i++) {
        int n = g_sortA[base + i];
        float2 v = *(const float2*)(xb + (size_t)n * 64);
        ax += v.x; ay += v.y;
    }
    float s = (cnt > 0) ? 1.f / (float)cnt : 0.f;
    *(float2*)&g_aggA[((size_t)t * NH + h) * 64 + lane * 2] = make_float2(ax * s, ay * s);
}

// ---------------- GEMM: efm = aggA @ Wcomb_t   (M=NH per type, N=64, K=64) --
__global__ __launch_bounds__(256) void k_mma_ef() {
    __shared__ __align__(16) float As[128][32];
    __shared__ __align__(16) float Bs[64][32];
    int tid = threadIdx.x;
    int lane = tid & 31, warp = tid >> 5;
    int warpM = warp >> 1, warpN = warp & 1;
    int g = lane >> 2, t4 = lane & 3;
    int rot = (g & 3) << 3;
    int n0 = blockIdx.x * 128;
    int ty = blockIdx.y;
    float acc[2][4][4] = {};
    for (int kc = 0; kc < 2; kc++) {
        __syncthreads();
        for (int i = tid; i < 4096; i += 256) {
            int m = i >> 5, kk = i & 31;
            int n = n0 + m;
            float v = (n < NH) ? g_aggA[((size_t)ty * NH + n) * 64 + kc * 32 + kk] : 0.f;
            As[m][swz(kk, m)] = to_tf32(v);
        }
        const float4* src = (const float4*)&g_Bef[(ty * 2 + kc) * 2048];
        float4* dst = (float4*)&Bs[0][0];
        for (int i = tid; i < 512; i += 256) dst[i] = src[i];
        __syncthreads();
#pragma unroll
        for (int s = 0; s < 4; s++) {
            int pc = (s * 8 + 2 * t4 + rot) & 31;
            uint32_t a[2][4];
#pragma unroll
            for (int mt = 0; mt < 2; mt++) {
                int r = warpM * 32 + mt * 16 + g;
                float2 lo = *(const float2*)&As[r][pc];
                float2 hi = *(const float2*)&As[r + 8][pc];
                a[mt][0] = __float_as_uint(lo.x); a[mt][1] = __float_as_uint(hi.x);
                a[mt][2] = __float_as_uint(lo.y); a[mt][3] = __float_as_uint(hi.y);
            }
#pragma unroll
            for (int nt = 0; nt < 4; nt++) {
                int c = warpN * 32 + nt * 8 + g;
                float2 b = *(const float2*)&Bs[c][pc];
                uint32_t b0 = __float_as_uint(b.x), b1 = __float_as_uint(b.y);
                mma_tf32(acc[0][nt], a[0], b0, b1);
                mma_tf32(acc[1][nt], a[1], b0, b1);
            }
        }
    }
#pragma unroll
    for (int mt = 0; mt < 2; mt++) {
        int r = n0 + warpM * 32 + mt * 16 + g;
#pragma unroll
        for (int nt = 0; nt < 4; nt++) {
            int c = warpN * 32 + nt * 8 + 2 * t4;
            if (r < NH)
                *(float2*)&g_efm[((size_t)ty * NH + r) * 64 + c] =
                    make_float2(acc[mt][nt][0], acc[mt][nt][1]);
            if (r + 8 < NH)
                *(float2*)&g_efm[((size_t)ty * NH + r + 8) * 64 + c] =
                    make_float2(acc[mt][nt][2], acc[mt][nt][3]);
        }
    }
}

// ---------------- gather B: h[n] = relu(sum_t Dinv_t * sum efm + bcmix) -----
__global__ __launch_bounds__(256) void k_gatherB() {
    int node = (blockIdx.x * 256 + threadIdx.x) >> 5;
    if (node >= NN) return;
    int lane = threadIdx.x & 31;
    const float* eb = g_efm + lane * 2;
    float ax = 0.f, ay = 0.f;
#pragma unroll
    for (int t = 0; t < 2; t++) {
        int key = node * 2 + t;
        int base = g_offB[key], cnt = g_cntB[key];
        float sx = 0.f, sy = 0.f;
        int i = 0;
        for (; i + 8 <= cnt; i += 8) {
            float2 v[8];
#pragma unroll
            for (int q = 0; q < 8; q++) {
                int o = g_sortB[base + i + q];
                v[q] = *(const float2*)(eb + o);
            }
#pragma unroll
            for (int q = 0; q < 8; q++) { sx += v[q].x; sy += v[q].y; }
        }
        for (; i < cnt; i++) {
            int o = g_sortB[base + i];
            float2 v = *(const float2*)(eb + o);
            sx += v.x; sy += v.y;
        }
        float s = (cnt > 0) ? 1.f / (float)cnt : 0.f;
        ax += sx * s; ay += sy * s;
    }
    float b0 = g_bcmix[lane * 2], b1 = g_bcmix[lane * 2 + 1];
    *(float2*)&g_h[(size_t)node * 64 + lane * 2] =
        make_float2(fmaxf(ax + b0, 0.f), fmaxf(ay + b1, 0.f));
}

// ---------------- persistent GRU: B-resident + cp.async pipelined A ---------
// smem floats: Ball[4][256][36]=36864 | As[2][128][36]=9216 | Wro3 256 | sred 512
//              | Hs[128][68]=8704  (h_prev in / h_next out staging)
#define OF_AS   36864
#define OF_WRO  46080
#define OF_SRED 46336
#define OF_HS   46848
#define GRU_SMEM ((46848 + 8704) * 4)
__global__ __launch_bounds__(512) void k_gru(const float* __restrict__ h_prev,
                                             const float* __restrict__ Wro,
                                             const float* __restrict__ bro,
                                             float* __restrict__ out_h,
                                             float* __restrict__ out3) {
    extern __shared__ __align__(16) float sm[];
    uint32_t smb;
    asm("{ .reg .u64 t; cvta.to.shared.u64 t, %1; cvt.u32.u64 %0, t; }"
        : "=r"(smb) : "l"(sm));
    int tid = threadIdx.x;
    int lane = tid & 31, warp = tid >> 5;
    int warpM = warp >> 2, warpN = warp & 3;
    int g = lane >> 2, t = lane & 3;

    // load all of B (147456 B) — once per CTA
    for (int i = tid; i < 9216; i += 512)
        cp16(smb + (uint32_t)i * 16, (const char*)g_Bgru + (size_t)i * 16);
    CP_COMMIT();

    if (tid < 256) {
        int j = tid >> 2, c = tid & 3;
        sm[OF_WRO + tid] = (c < 3) ? __ldg(&Wro[j * 64 + c]) : 0.f;
    }
    sm[OF_SRED + tid] = 0.f;
    float brd0 = __ldg(&bro[0]), brd1 = __ldg(&bro[1]), brd2 = __ldg(&bro[2]);

#define STAGE_A(ptile, pkc) do {                                               \
        int _kc = (pkc);                                                       \
        uint32_t _dst = smb + (OF_AS + (_kc & 1) * 4608) * 4;                  \
        for (int i = tid; i < 1024; i += 512) {                                \
            int m = i >> 3, q = i & 7;                                         \
            int n = (ptile) * 128 + m;                                         \
            int nc = (n < NN) ? n : (NN - 1);                                  \
            const float* src = (_kc < 2)                                       \
                ? &g_h[(size_t)nc * 64 + _kc * 32 + q * 4]                     \
                : &h_prev[(size_t)nc * 64 + (_kc - 2) * 32 + q * 4];           \
            cp16(_dst + (uint32_t)(m * 144 + q * 16), src);                    \
        }                                                                      \
    } while (0)

    int tile = blockIdx.x;
    if (tile < NT) STAGE_A(tile, 0);
    CP_COMMIT();

    for (; tile < NT; tile += GRID_GRU) {
        int n0 = tile * 128;
        float acc[2][8][4] = {};
        for (int kc = 0; kc < 4; kc++) {
            CP_WAIT0();
            __syncthreads();
            {
                int nk = kc + 1, pt = tile;
                if (nk == 4) { nk = 0; pt = tile + GRID_GRU; }
                if (pt < NT) STAGE_A(pt, nk);
                CP_COMMIT();
            }
            const float* As = sm + OF_AS + (kc & 1) * 4608;
            const float* Bb = sm + kc * 9216;
#pragma unroll
            for (int s = 0; s < 4; s++) {
                int k0 = s * 8;
                uint32_t a[2][4];
#pragma unroll
                for (int mt = 0; mt < 2; mt++) {
                    int r = warpM * 32 + mt * 16 + g;
                    a[mt][0] = __float_as_uint(As[r * 36 + k0 + t]);
                    a[mt][1] = __float_as_uint(As[(r + 8) * 36 + k0 + t]);
                    a[mt][2] = __float_as_uint(As[r * 36 + k0 + t + 4]);
                    a[mt][3] = __float_as_uint(As[(r + 8) * 36 + k0 + t + 4]);
                }
#pragma unroll
                for (int nt = 0; nt < 8; nt++) {
                    int c = warpN * 64 + nt * 8 + g;
                    float2 bb = *(const float2*)&Bb[c * 36 + k0 + 2 * t];
                    mma_tf32(acc[0][nt], a[0],
                             __float_as_uint(bb.x), __float_as_uint(bb.y));
                    mma_tf32(acc[1][nt], a[1],
                             __float_as_uint(bb.x), __float_as_uint(bb.y));
                }
            }
        }

        // ---- phase 1: coalesced h_prev tile -> Hs ----
        for (int i = tid; i < 2048; i += 512) {
            int m = i >> 4, q = i & 15;
            int n = n0 + m;
            float4 v = make_float4(0.f, 0.f, 0.f, 0.f);
            if (n < NN) v = *(const float4*)&h_prev[(size_t)n * 64 + q * 4];
            *(float4*)&sm[OF_HS + m * 68 + q * 4] = v;
        }
        __syncthreads();

        // ---- phase 2: gate epilogue (SMEM in-place) + readout partials ----
        float p[2][2][3] = {};
        bool even = (t & 1) == 0;
#pragma unroll
        for (int mt = 0; mt < 2; mt++) {
#pragma unroll
            for (int nt = 0; nt < 8; nt++) {
                int j = warpN * 16 + nt * 2 + (t >> 1);
                float br = g_bias[j], bz = g_bias[64 + j];
                float bn = g_bias[128 + j], bh = g_bias[192 + j];
                float w0 = sm[OF_WRO + j * 4 + 0];
                float w1 = sm[OF_WRO + j * 4 + 1];
                float w2 = sm[OF_WRO + j * 4 + 2];
#pragma unroll
                for (int rh = 0; rh < 2; rh++) {
                    int m = warpM * 32 + mt * 16 + rh * 8 + g;
                    float v0 = acc[mt][nt][rh * 2 + 0];
                    float v1 = acc[mt][nt][rh * 2 + 1];
                    float o0 = __shfl_xor_sync(0xffffffffu, v0, 1);
                    float o1 = __shfl_xor_sync(0xffffffffu, v1, 1);
                    float hn = 0.f;
                    if (even) {
                        float r_ = sigf(v0 + br);
                        float z_ = sigf(v1 + bz);
                        float nv = tanh_fast((o0 + bn) + r_ * (o1 + bh));
                        float hp = sm[OF_HS + m * 68 + j];
                        hn = (1.f - z_) * nv + z_ * hp;
                        sm[OF_HS + m * 68 + j] = hn;
                    }
                    p[mt][rh][0] += hn * w0;
                    p[mt][rh][1] += hn * w1;
                    p[mt][rh][2] += hn * w2;
                }
            }
        }
#pragma unroll
        for (int mt = 0; mt < 2; mt++)
#pragma unroll
            for (int rh = 0; rh < 2; rh++)
#pragma unroll
                for (int c = 0; c < 3; c++) {
                    float v = p[mt][rh][c] + __shfl_xor_sync(0xffffffffu, p[mt][rh][c], 2);
                    if (t == 0)
                        atomicAdd(&sm[OF_SRED + (warpM * 32 + mt * 16 + rh * 8 + g) * 4 + c], v);
                }
        __syncthreads();

        // ---- phase 3: coalesced Hs -> out_h, plus out3 ----
        for (int i = tid; i < 2048; i += 512) {
            int m = i >> 4, q = i & 15;
            int n = n0 + m;
            if (n < NN)
                *(float4*)&out_h[(size_t)n * 64 + q * 4] =
                    *(const float4*)&sm[OF_HS + m * 68 + q * 4];
        }
        {
            int nd = tid >> 2, c = tid & 3;
            int n = n0 + nd;
            if (c < 3 && n < NN)
                out3[(size_t)n * 3 + c] = sm[OF_SRED + tid] +
                                          (c == 0 ? brd0 : (c == 1 ? brd1 : brd2));
        }
        __syncthreads();
        sm[OF_SRED + tid] = 0.f;
    }
#undef STAGE_A
}

// ---------------- launch -----------------------------------------------------
extern "C" void kernel_launch(void* const* d_in, const int* in_sizes, int n_in,
                              void* d_out, int out_size) {
    const float* x       = (const float*)d_in[0];
    const float* h_prev  = (const float*)d_in[1];
    const int* node_idx  = (const int*)d_in[2];
    const int* hedge_idx = (const int*)d_in[3];
    const int* edge_attr = (const int*)d_in[4];
    const float* W_conv  = (const float*)d_in[5];
    const float* b_conv  = (const float*)d_in[6];
    const float* W_mix   = (const float*)d_in[7];
    const float* b_mix   = (const float*)d_in[8];
    const float* W_ih    = (const float*)d_in[9];
    const float* W_hh    = (const float*)d_in[10];
    const float* b_ih    = (const float*)d_in[11];
    const float* b_hh    = (const float*)d_in[12];
    const float* W_ro    = (const float*)d_in[13];
    const float* b_ro    = (const float*)d_in[14];

    float* h_next = (float*)d_out;
    float* out3   = (float*)d_out + (size_t)NN * 64;

    cudaFuncSetAttribute(k_gru, cudaFuncAttributeMaxDynamicSharedMemorySize, GRU_SMEM);

    k_zero_cnt<<<(NKB + 255) / 256, 256>>>();
    k_prep_hist<<<(NE4 + 255) / 256, 256>>>(W_conv, W_mix, b_mix, b_conv,
                                            W_ih, W_hh, b_ih, b_hh,
                                            node_idx, hedge_idx, edge_attr);
    k_offsets<<<NBA + NBB, 1024>>>();
    k_perm<<<(NE4 + 255) / 256, 256>>>(node_idx, hedge_idx, edge_attr);
    k_gatherA<<<(NKA * 32 + 255) / 256, 256>>>(x);
    k_mma_ef<<<dim3((NH + 127) / 128, 2), 256>>>();
    k_gatherB<<<(NN * 32 + 255) / 256, 256>>>();
    k_gru<<<GRID_GRU, 512, GRU_SMEM>>>(h_prev, W_ro, b_ro, h_next, out3);
}

// round 12
// speedup vs baseline: 1.5862x; 1.0157x over previous
#include <cuda_runtime.h>
#include <cstdint>

#define NN 100000
#define NH 20000
#define NE 800000
#define NE4 (NE/4)
#define NKA (NH*2)     // hedge-type keys
#define NKB (NN*2)     // node-type keys
#define NBA ((NKA + 1023) / 1024)
#define NBB ((NKB + 1023) / 1024)
#define NT  ((NN + 127) / 128)   // 782 GRU tiles
#define GRID_GRU 152

// ---------------- static device buffers ------------------------------------
__device__ __align__(16) float g_aggA[(size_t)2*NH*64];  // (Σx)/cnt per (t,h)
__device__ __align__(16) float g_efm[(size_t)2*NH*64];   // aggA @ Wcomb_t
__device__ __align__(16) float g_h[(size_t)NN*64];       // relu(mix)
__device__ int g_cntA[NKA], g_offA[NKA];
__device__ int g_cntB[NKB], g_offB[NKB];
__device__ int g_baseA, g_baseB;
__device__ __align__(16) int g_rankA[NE], g_rankB[NE];
__device__ int g_sortA[NE];   // node ids, sorted by (hedge,type)
__device__ int g_sortB[NE];   // efm row offsets (floats), sorted by (node,type)
// B images
__device__ __align__(16) float g_Bef[2*2*64*32];        // Wcomb_t (swizzled, tf32)
__device__ __align__(16) float g_Bgru[4*256*36];        // GRU B, pitch-36, pair-permuted k
__device__ float g_bias[256];
__device__ float g_bcmix[64];

// ---------------- helpers ---------------------------------------------------
__device__ __forceinline__ float to_tf32(float v) {
    uint32_t u; asm("cvt.rna.tf32.f32 %0, %1;" : "=r"(u) : "f"(v));
    return __uint_as_float(u);
}
__device__ __forceinline__ int swz(int kk, int row) {
    int r = kk & 7;
    int pos = (r < 4) ? (r * 2) : ((r - 4) * 2 + 1);
    int sc = (kk & 24) + pos;
    return (sc + ((row & 3) << 3)) & 31;
}
__device__ __forceinline__ void mma_tf32(float* c, const uint32_t* a,
                                         uint32_t b0, uint32_t b1) {
    asm volatile(
        "mma.sync.aligned.m16n8k8.row.col.f32.tf32.tf32.f32 "
        "{%0,%1,%2,%3}, {%4,%5,%6,%7}, {%8,%9}, {%0,%1,%2,%3};"
        : "+f"(c[0]), "+f"(c[1]), "+f"(c[2]), "+f"(c[3])
        : "r"(a[0]), "r"(a[1]), "r"(a[2]), "r"(a[3]), "r"(b0), "r"(b1));
}
__device__ __forceinline__ float sigf(float x) { return 1.f / (1.f + __expf(-x)); }
__device__ __forceinline__ float tanh_fast(float x) {
    return 1.f - 2.f / (__expf(2.f * x) + 1.f);
}
__device__ __forceinline__ void cp16(uint32_t dst, const void* src) {
    asm volatile("cp.async.cg.shared.global [%0], [%1], 16;" :: "r"(dst), "l"(src));
}
#define CP_COMMIT() asm volatile("cp.async.commit_group;" ::: "memory")
#define CP_WAIT0()  asm volatile("cp.async.wait_group 0;" ::: "memory")

// ---------------- merged prep + histogram -----------------------------------
__global__ void k_prep_hist(const float* __restrict__ Wc, const float* __restrict__ Wmix,
                            const float* __restrict__ bmix, const float* __restrict__ bconv,
                            const float* __restrict__ Wih, const float* __restrict__ Whh,
                            const float* __restrict__ bih, const float* __restrict__ bhh,
                            const int* __restrict__ ni, const int* __restrict__ hi,
                            const int* __restrict__ ea) {
    int idx = blockIdx.x * blockDim.x + threadIdx.x;
    if (idx == 0) { g_baseA = 0; g_baseB = 0; }

    if (idx < 8192) {                     // Bef: [2][2 kc][64 c][32] (swizzled)
        int t = idx >> 12, rem = idx & 4095;
        int kc = rem >> 11, rem2 = rem & 2047, c = rem2 >> 5, kk = rem2 & 31;
        int k = kc * 32 + kk;
        float s = 0.f;
        const float* wr = Wc + t * 4096 + k * 64;
        const float* wm = Wmix + (size_t)t * 64 * 64 + c;
#pragma unroll 8
        for (int m = 0; m < 64; m++) s += wr[m] * wm[(size_t)m * 64];
        g_Bef[((t * 2 + kc) * 64 + c) * 32 + swz(kk, c)] = to_tf32(s);
    } else if (idx < 8192 + 36864) {      // Bgru: [4 kc][256 c][36], pair-permuted k
        int i = idx - 8192;
        int kc = i / 9216, rem = i - kc * 9216;
        int c = rem / 36, kkp = rem - c * 36;
        float v = 0.f;
        if (kkp < 32) {
            int k0 = kkp & ~7, r = kkp & 7;
            int kk = k0 + (r >> 1) + ((r & 1) ? 4 : 0);
            int k = kc * 32 + kk;
            int j = c >> 2, seg = c & 3;
            if (k < 64) {
                if (seg == 0)      v = Wih[k * 192 + j];
                else if (seg == 1) v = Wih[k * 192 + 64 + j];
                else if (seg == 2) v = Wih[k * 192 + 128 + j];
            } else {
                int k2 = k - 64;
                if (seg == 0)      v = Whh[k2 * 192 + j];
                else if (seg == 1) v = Whh[k2 * 192 + 64 + j];
                else if (seg == 3) v = Whh[k2 * 192 + 128 + j];
            }
        }
        g_Bgru[i] = to_tf32(v);
    } else if (idx < 45056 + 256) {       // GRU bias (seg-major)
        int c = idx - 45056;
        int seg = c >> 6, j = c & 63;
        float b;
        if (seg == 0)      b = bih[j] + bhh[j];
        else if (seg == 1) b = bih[64 + j] + bhh[64 + j];
        else if (seg == 2) b = bih[128 + j];
        else               b = bhh[128 + j];
        g_bias[c] = b;
    } else if (idx < 45056 + 256 + 64) {  // folded mix bias
        int j = idx - 45056 - 256;
        float s = bmix[j];
        for (int k = 0; k < 128; k++) s += bconv[k] * Wmix[k * 64 + j];
        g_bcmix[j] = s;
    }

    if (idx < NE4) {
        int4 n = ((const int4*)ni)[idx];
        int4 h = ((const int4*)hi)[idx];
        int4 t = ((const int4*)ea)[idx];
        int4 ra, rb;
        ra.x = atomicAdd(&g_cntA[h.x * 2 + t.x], 1);
        ra.y = atomicAdd(&g_cntA[h.y * 2 + t.y], 1);
        ra.z = atomicAdd(&g_cntA[h.z * 2 + t.z], 1);
        ra.w = atomicAdd(&g_cntA[h.w * 2 + t.w], 1);
        rb.x = atomicAdd(&g_cntB[n.x * 2 + t.x], 1);
        rb.y = atomicAdd(&g_cntB[n.y * 2 + t.y], 1);
        rb.z = atomicAdd(&g_cntB[n.z * 2 + t.z], 1);
        rb.w = atomicAdd(&g_cntB[n.w * 2 + t.w], 1);
        ((int4*)g_rankA)[idx] = ra;
        ((int4*)g_rankB)[idx] = rb;
    }
}

// ---------------- zero counters (runs before prep_hist) ---------------------
__global__ void k_zero_cnt() {
    int i = blockIdx.x * 256 + threadIdx.x;
    if (i < NKA) g_cntA[i] = 0;
    if (i < NKB) g_cntB[i] = 0;
}

// ---------------- parallel offsets: block scan + atomic range claim ---------
__global__ __launch_bounds__(1024) void k_offsets() {
    __shared__ int sm[1024];
    __shared__ int blockBase;
    int b = blockIdx.x;
    const int* cnt; int* off; int n; int* gbase;
    if (b < NBA) { cnt = g_cntA; off = g_offA; n = NKA; gbase = &g_baseA; }
    else { b -= NBA; cnt = g_cntB; off = g_offB; n = NKB; gbase = &g_baseB; }
    int tid = threadIdx.x;
    int i = b * 1024 + tid;
    int v = (i < n) ? cnt[i] : 0;
    sm[tid] = v;
    __syncthreads();
    for (int d = 1; d < 1024; d <<= 1) {
        int t = (tid >= d) ? sm[tid - d] : 0;
        __syncthreads();
        sm[tid] += t;
        __syncthreads();
    }
    if (tid == 1023) blockBase = atomicAdd(gbase, sm[1023]);
    __syncthreads();
    if (i < n) off[i] = blockBase + sm[tid] - v;
}

// ---------------- permute: atomic-free scatter, 4 edges/thread --------------
__global__ void k_perm(const int* __restrict__ ni, const int* __restrict__ hi,
                       const int* __restrict__ ea) {
    int i = blockIdx.x * 256 + threadIdx.x;
    if (i >= NE4) return;
    int4 n = ((const int4*)ni)[i];
    int4 h = ((const int4*)hi)[i];
    int4 t = ((const int4*)ea)[i];
    int4 ra = ((const int4*)g_rankA)[i];
    int4 rb = ((const int4*)g_rankB)[i];
    g_sortA[g_offA[h.x * 2 + t.x] + ra.x] = n.x;
    g_sortA[g_offA[h.y * 2 + t.y] + ra.y] = n.y;
    g_sortA[g_offA[h.z * 2 + t.z] + ra.z] = n.z;
    g_sortA[g_offA[h.w * 2 + t.w] + ra.w] = n.w;
    g_sortB[g_offB[n.x * 2 + t.x] + rb.x] = (t.x * NH + h.x) * 64;
    g_sortB[g_offB[n.y * 2 + t.y] + rb.y] = (t.y * NH + h.y) * 64;
    g_sortB[g_offB[n.z * 2 + t.z] + rb.z] = (t.z * NH + h.z) * 64;
    g_sortB[g_offB[n.w * 2 + t.w] + rb.w] = (t.w * NH + h.w) * 64;
}

// ---------------- gather A: half-warp per row, float4 lanes -----------------
__global__ __launch_bounds__(256) void k_gatherA(const float* __restrict__ x) {
    int key = (blockIdx.x * 256 + threadIdx.x) >> 5;
    if (key >= NKA) return;
    int lane = threadIdx.x & 31;
    int half = lane >> 4, sub = lane & 15;
    int t = key & 1, h = key >> 1;
    int base = g_offA[key], cnt = g_cntA[key];
    const float* xb = x + sub * 4;
    float4 acc = make_float4(0.f, 0.f, 0.f, 0.f);
    int i = 0;
    for (; i + 4 <= cnt; i += 4) {
        int n0 = g_sortA[base + i + half];
        int n1 = g_sortA[base + i + 2 + half];
        float4 v0 = *(const float4*)(xb + (size_t)n0 * 64);
        float4 v1 = *(const float4*)(xb + (size_t)n1 * 64);
        acc.x += v0.x + v1.x; acc.y += v0.y + v1.y;
        acc.z += v0.z + v1.z; acc.w += v0.w + v1.w;
    }
    for (; i < cnt; i += 2) {
        int idx = i + half;
        if (idx < cnt) {
            int n = g_sortA[base + idx];
            float4 v = *(const float4*)(xb + (size_t)n * 64);
            acc.x += v.x; acc.y += v.y; acc.z += v.z; acc.w += v.w;
        }
    }
    acc.x += __shfl_xor_sync(0xffffffffu, acc.x, 16);
    acc.y += __shfl_xor_sync(0xffffffffu, acc.y, 16);
    acc.z += __shfl_xor_sync(0xffffffffu, acc.z, 16);
    acc.w += __shfl_xor_sync(0xffffffffu, acc.w, 16);
    if (half == 0) {
        float s = (cnt > 0) ? 1.f / (float)cnt : 0.f;
        acc.x *= s; acc.y *= s; acc.z *= s; acc.w *= s;
        *(float4*)&g_aggA[((size_t)t * NH + h) * 64 + sub * 4] = acc;
    }
}

// ---------------- GEMM: efm = aggA @ Wcomb_t   (M=NH per type, N=64, K=64) --
__global__ __launch_bounds__(256) void k_mma_ef() {
    __shared__ __align__(16) float As[128][32];
    __shared__ __align__(16) float Bs[64][32];
    int tid = threadIdx.x;
    int lane = tid & 31, warp = tid >> 5;
    int warpM = warp >> 1, warpN = warp & 1;
    int g = lane >> 2, t4 = lane & 3;
    int rot = (g & 3) << 3;
    int n0 = blockIdx.x * 128;
    int ty = blockIdx.y;
    float acc[2][4][4] = {};
    for (int kc = 0; kc < 2; kc++) {
        __syncthreads();
        for (int i = tid; i < 4096; i += 256) {
            int m = i >> 5, kk = i & 31;
            int n = n0 + m;
            float v = (n < NH) ? g_aggA[((size_t)ty * NH + n) * 64 + kc * 32 + kk] : 0.f;
            As[m][swz(kk, m)] = to_tf32(v);
        }
        const float4* src = (const float4*)&g_Bef[(ty * 2 + kc) * 2048];
        float4* dst = (float4*)&Bs[0][0];
        for (int i = tid; i < 512; i += 256) dst[i] = src[i];
        __syncthreads();
#pragma unroll
        for (int s = 0; s < 4; s++) {
            int pc = (s * 8 + 2 * t4 + rot) & 31;
            uint32_t a[2][4];
#pragma unroll
            for (int mt = 0; mt < 2; mt++) {
                int r = warpM * 32 + mt * 16 + g;
                float2 lo = *(const float2*)&As[r][pc];
                float2 hi = *(const float2*)&As[r + 8][pc];
                a[mt][0] = __float_as_uint(lo.x); a[mt][1] = __float_as_uint(hi.x);
                a[mt][2] = __float_as_uint(lo.y); a[mt][3] = __float_as_uint(hi.y);
            }
#pragma unroll
            for (int nt = 0; nt < 4; nt++) {
                int c = warpN * 32 + nt * 8 + g;
                float2 b = *(const float2*)&Bs[c][pc];
                uint32_t b0 = __float_as_uint(b.x), b1 = __float_as_uint(b.y);
                mma_tf32(acc[0][nt], a[0], b0, b1);
                mma_tf32(acc[1][nt], a[1], b0, b1);
            }
        }
    }
#pragma unroll
    for (int mt = 0; mt < 2; mt++) {
        int r = n0 + warpM * 32 + mt * 16 + g;
#pragma unroll
        for (int nt = 0; nt < 4; nt++) {
            int c = warpN * 32 + nt * 8 + 2 * t4;
            if (r < NH)
                *(float2*)&g_efm[((size_t)ty * NH + r) * 64 + c] =
                    make_float2(acc[mt][nt][0], acc[mt][nt][1]);
            if (r + 8 < NH)
                *(float2*)&g_efm[((size_t)ty * NH + r + 8) * 64 + c] =
                    make_float2(acc[mt][nt][2], acc[mt][nt][3]);
        }
    }
}

// ---------------- gather B: half-warp per row, float4 lanes -----------------
__global__ __launch_bounds__(256) void k_gatherB() {
    int node = (blockIdx.x * 256 + threadIdx.x) >> 5;
    if (node >= NN) return;
    int lane = threadIdx.x & 31;
    int half = lane >> 4, sub = lane & 15;
    const float* eb = g_efm + sub * 4;
    float4 tot = make_float4(0.f, 0.f, 0.f, 0.f);
#pragma unroll
    for (int t = 0; t < 2; t++) {
        int key = node * 2 + t;
        int base = g_offB[key], cnt = g_cntB[key];
        float4 acc = make_float4(0.f, 0.f, 0.f, 0.f);
        int i = 0;
        for (; i + 4 <= cnt; i += 4) {
            int o0 = g_sortB[base + i + half];
            int o1 = g_sortB[base + i + 2 + half];
            float4 v0 = *(const float4*)(eb + o0);
            float4 v1 = *(const float4*)(eb + o1);
            acc.x += v0.x + v1.x; acc.y += v0.y + v1.y;
            acc.z += v0.z + v1.z; acc.w += v0.w + v1.w;
        }
        for (; i < cnt; i += 2) {
            int idx = i + half;
            if (idx < cnt) {
                int o = g_sortB[base + idx];
                float4 v = *(const float4*)(eb + o);
                acc.x += v.x; acc.y += v.y; acc.z += v.z; acc.w += v.w;
            }
        }
        float s = (cnt > 0) ? 1.f / (float)cnt : 0.f;
        tot.x += acc.x * s; tot.y += acc.y * s;
        tot.z += acc.z * s; tot.w += acc.w * s;
    }
    tot.x += __shfl_xor_sync(0xffffffffu, tot.x, 16);
    tot.y += __shfl_xor_sync(0xffffffffu, tot.y, 16);
    tot.z += __shfl_xor_sync(0xffffffffu, tot.z, 16);
    tot.w += __shfl_xor_sync(0xffffffffu, tot.w, 16);
    if (half == 0) {
        float4 b = *(const float4*)&g_bcmix[sub * 4];
        float4 o;
        o.x = fmaxf(tot.x + b.x, 0.f); o.y = fmaxf(tot.y + b.y, 0.f);
        o.z = fmaxf(tot.z + b.z, 0.f); o.w = fmaxf(tot.w + b.w, 0.f);
        *(float4*)&g_h[(size_t)node * 64 + sub * 4] = o;
    }
}

// ---------------- persistent GRU: B-resident + cp.async pipelined A ---------
// smem floats: Ball[4][256][36]=36864 | As[2][128][36]=9216 | Wro3 256 | sred 512
//              | Hs[128][68]=8704  (h_next output staging)
#define OF_AS   36864
#define OF_WRO  46080
#define OF_SRED 46336
#define OF_HS   46848
#define GRU_SMEM ((46848 + 8704) * 4)
__global__ __launch_bounds__(512) void k_gru(const float* __restrict__ h_prev,
                                             const float* __restrict__ Wro,
                                             const float* __restrict__ bro,
                                             float* __restrict__ out_h,
                                             float* __restrict__ out3) {
    extern __shared__ __align__(16) float sm[];
    uint32_t smb;
    asm("{ .reg .u64 t; cvta.to.shared.u64 t, %1; cvt.u32.u64 %0, t; }"
        : "=r"(smb) : "l"(sm));
    int tid = threadIdx.x;
    int lane = tid & 31, warp = tid >> 5;
    int warpM = warp >> 2, warpN = warp & 3;
    int g = lane >> 2, t = lane & 3;

    // load all of B (147456 B) — once per CTA
    for (int i = tid; i < 9216; i += 512)
        cp16(smb + (uint32_t)i * 16, (const char*)g_Bgru + (size_t)i * 16);
    CP_COMMIT();

    if (tid < 256) {
        int j = tid >> 2, c = tid & 3;
        sm[OF_WRO + tid] = (c < 3) ? __ldg(&Wro[j * 64 + c]) : 0.f;
    }
    sm[OF_SRED + tid] = 0.f;
    float brd0 = __ldg(&bro[0]), brd1 = __ldg(&bro[1]), brd2 = __ldg(&bro[2]);

#define STAGE_A(ptile, pkc) do {                                               \
        int _kc = (pkc);                                                       \
        uint32_t _dst = smb + (OF_AS + (_kc & 1) * 4608) * 4;                  \
        for (int i = tid; i < 1024; i += 512) {                                \
            int m = i >> 3, q = i & 7;                                         \
            int n = (ptile) * 128 + m;                                         \
            int nc = (n < NN) ? n : (NN - 1);                                  \
            const float* src = (_kc < 2)                                       \
                ? &g_h[(size_t)nc * 64 + _kc * 32 + q * 4]                     \
                : &h_prev[(size_t)nc * 64 + (_kc - 2) * 32 + q * 4];           \
            cp16(_dst + (uint32_t)(m * 144 + q * 16), src);                    \
        }                                                                      \
    } while (0)

    int tile = blockIdx.x;
    if (tile < NT) STAGE_A(tile, 0);
    CP_COMMIT();

    for (; tile < NT; tile += GRID_GRU) {
        int n0 = tile * 128;
        float acc[2][8][4] = {};
        for (int kc = 0; kc < 4; kc++) {
            CP_WAIT0();
            __syncthreads();
            if (kc < 3) { STAGE_A(tile, kc + 1); CP_COMMIT(); }
            const float* As = sm + OF_AS + (kc & 1) * 4608;
            const float* Bb = sm + kc * 9216;
#pragma unroll
            for (int s = 0; s < 4; s++) {
                int k0 = s * 8;
                uint32_t a[2][4];
#pragma unroll
                for (int mt = 0; mt < 2; mt++) {
                    int r = warpM * 32 + mt * 16 + g;
                    a[mt][0] = __float_as_uint(As[r * 36 + k0 + t]);
                    a[mt][1] = __float_as_uint(As[(r + 8) * 36 + k0 + t]);
                    a[mt][2] = __float_as_uint(As[r * 36 + k0 + t + 4]);
                    a[mt][3] = __float_as_uint(As[(r + 8) * 36 + k0 + t + 4]);
                }
#pragma unroll
                for (int nt = 0; nt < 8; nt++) {
                    int c = warpN * 64 + nt * 8 + g;
                    float2 bb = *(const float2*)&Bb[c * 36 + k0 + 2 * t];
                    mma_tf32(acc[0][nt], a[0],
                             __float_as_uint(bb.x), __float_as_uint(bb.y));
                    mma_tf32(acc[1][nt], a[1],
                             __float_as_uint(bb.x), __float_as_uint(bb.y));
                }
            }
        }

        // ---- gate epilogue: hp from As bufs (h_prev resident), hn -> Hs ----
        // As buf0 = h_prev[:, 0:32), buf1 = h_prev[:, 32:64) for this tile.
        const float* Ab0 = sm + OF_AS;
        const float* Ab1 = sm + OF_AS + 4608;
        float p[2][2][3] = {};
        bool even = (t & 1) == 0;
#pragma unroll
        for (int mt = 0; mt < 2; mt++) {
#pragma unroll
            for (int nt = 0; nt < 8; nt++) {
                int j = warpN * 16 + nt * 2 + (t >> 1);
                float br = g_bias[j], bz = g_bias[64 + j];
                float bn = g_bias[128 + j], bh = g_bias[192 + j];
                float w0 = sm[OF_WRO + j * 4 + 0];
                float w1 = sm[OF_WRO + j * 4 + 1];
                float w2 = sm[OF_WRO + j * 4 + 2];
#pragma unroll
                for (int rh = 0; rh < 2; rh++) {
                    int m = warpM * 32 + mt * 16 + rh * 8 + g;
                    float v0 = acc[mt][nt][rh * 2 + 0];
                    float v1 = acc[mt][nt][rh * 2 + 1];
                    float o0 = __shfl_xor_sync(0xffffffffu, v0, 1);
                    float o1 = __shfl_xor_sync(0xffffffffu, v1, 1);
                    float hn = 0.f;
                    if (even) {
                        float r_ = sigf(v0 + br);
                        float z_ = sigf(v1 + bz);
                        float nv = tanh_fast((o0 + bn) + r_ * (o1 + bh));
                        float hp = (j < 32) ? Ab0[m * 36 + j] : Ab1[m * 36 + j - 32];
                        hn = (1.f - z_) * nv + z_ * hp;
                        sm[OF_HS + m * 68 + j] = hn;
                    }
                    p[mt][rh][0] += hn * w0;
                    p[mt][rh][1] += hn * w1;
                    p[mt][rh][2] += hn * w2;
                }
            }
        }
#pragma unroll
        for (int mt = 0; mt < 2; mt++)
#pragma unroll
            for (int rh = 0; rh < 2; rh++)
#pragma unroll
                for (int c = 0; c < 3; c++) {
                    float v = p[mt][rh][c] + __shfl_xor_sync(0xffffffffu, p[mt][rh][c], 2);
                    if (t == 0)
                        atomicAdd(&sm[OF_SRED + (warpM * 32 + mt * 16 + rh * 8 + g) * 4 + c], v);
                }
        __syncthreads();   // epilogue reads of As bufs + Hs/sred writes complete

        // prefetch next tile's first A chunk (overlaps the stores below)
        {
            int pt = tile + GRID_GRU;
            if (pt < NT) { STAGE_A(pt, 0); CP_COMMIT(); }
        }

        // ---- coalesced Hs -> out_h, plus out3 ----
        for (int i = tid; i < 2048; i += 512) {
            int m = i >> 4, q = i & 15;
            int n = n0 + m;
            if (n < NN)
                *(float4*)&out_h[(size_t)n * 64 + q * 4] =
                    *(const float4*)&sm[OF_HS + m * 68 + q * 4];
        }
        {
            int nd = tid >> 2, c = tid & 3;
            int n = n0 + nd;
            if (c < 3 && n < NN)
                out3[(size_t)n * 3 + c] = sm[OF_SRED + tid] +
                                          (c == 0 ? brd0 : (c == 1 ? brd1 : brd2));
        }
        __syncthreads();
        sm[OF_SRED + tid] = 0.f;
    }
#undef STAGE_A
}

// ---------------- launch -----------------------------------------------------
extern "C" void kernel_launch(void* const* d_in, const int* in_sizes, int n_in,
                              void* d_out, int out_size) {
    const float* x       = (const float*)d_in[0];
    const float* h_prev  = (const float*)d_in[1];
    const int* node_idx  = (const int*)d_in[2];
    const int* hedge_idx = (const int*)d_in[3];
    const int* edge_attr = (const int*)d_in[4];
    const float* W_conv  = (const float*)d_in[5];
    const float* b_conv  = (const float*)d_in[6];
    const float* W_mix   = (const float*)d_in[7];
    const float* b_mix   = (const float*)d_in[8];
    const float* W_ih    = (const float*)d_in[9];
    const float* W_hh    = (const float*)d_in[10];
    const float* b_ih    = (const float*)d_in[11];
    const float* b_hh    = (const float*)d_in[12];
    const float* W_ro    = (const float*)d_in[13];
    const float* b_ro    = (const float*)d_in[14];

    float* h_next = (float*)d_out;
    float* out3   = (float*)d_out + (size_t)NN * 64;

    cudaFuncSetAttribute(k_gru, cudaFuncAttributeMaxDynamicSharedMemorySize, GRU_SMEM);

    k_zero_cnt<<<(NKB + 255) / 256, 256>>>();
    k_prep_hist<<<(NE4 + 255) / 256, 256>>>(W_conv, W_mix, b_mix, b_conv,
                                            W_ih, W_hh, b_ih, b_hh,
                                            node_idx, hedge_idx, edge_attr);
    k_offsets<<<NBA + NBB, 1024>>>();
    k_perm<<<(NE4 + 255) / 256, 256>>>(node_idx, hedge_idx, edge_attr);
    k_gatherA<<<(NKA * 32 + 255) / 256, 256>>>(x);
    k_mma_ef<<<dim3((NH + 127) / 128, 2), 256>>>();
    k_gatherB<<<(NN * 32 + 255) / 256, 256>>>();
    k_gru<<<GRID_GRU, 512, GRU_SMEM>>>(h_prev, W_ro, b_ro, h_next, out3);
}

// round 13
// speedup vs baseline: 1.6553x; 1.0435x over previous
#include <cuda_runtime.h>
#include <cuda_fp16.h>
#include <cstdint>

#define NN 100000
#define NH 20000
#define NE 800000
#define NE4 (NE/4)
#define NKA (NH*2)     // hedge-type keys
#define NKB (NN*2)     // node-type keys
#define NBA ((NKA + 1023) / 1024)
#define NBB ((NKB + 1023) / 1024)
#define NT  ((NN + 127) / 128)   // 782 GRU tiles
#define GRID_GRU 152

// ---------------- static device buffers ------------------------------------
__device__ __align__(16) float g_aggA[(size_t)2*NH*64];   // (Σx)/cnt per (t,h)
__device__ __align__(16) __half g_efmh[(size_t)2*NH*64];  // aggA @ Wcomb_t (fp16)
__device__ __align__(16) float g_h[(size_t)NN*64];        // relu(mix)
__device__ int g_cntA[NKA], g_offA[NKA];
__device__ int g_cntB[NKB], g_offB[NKB];
__device__ int g_baseA, g_baseB;
__device__ __align__(16) int g_rankA[NE], g_rankB[NE];
__device__ int g_sortA[NE];   // node ids, sorted by (hedge,type)
__device__ int g_sortB[NE];   // efm element offsets, sorted by (node,type)
// B images
__device__ __align__(16) float g_Bef[2*2*64*32];        // Wcomb_t (swizzled, tf32)
__device__ __align__(16) float g_Bgru[4*256*36];        // GRU B, pitch-36, pair-permuted k
__device__ float g_bias[256];
__device__ float g_bcmix[64];

// ---------------- helpers ---------------------------------------------------
__device__ __forceinline__ float to_tf32(float v) {
    uint32_t u; asm("cvt.rna.tf32.f32 %0, %1;" : "=r"(u) : "f"(v));
    return __uint_as_float(u);
}
__device__ __forceinline__ int swz(int kk, int row) {
    int r = kk & 7;
    int pos = (r < 4) ? (r * 2) : ((r - 4) * 2 + 1);
    int sc = (kk & 24) + pos;
    return (sc + ((row & 3) << 3)) & 31;
}
__device__ __forceinline__ void mma_tf32(float* c, const uint32_t* a,
                                         uint32_t b0, uint32_t b1) {
    asm volatile(
        "mma.sync.aligned.m16n8k8.row.col.f32.tf32.tf32.f32 "
        "{%0,%1,%2,%3}, {%4,%5,%6,%7}, {%8,%9}, {%0,%1,%2,%3};"
        : "+f"(c[0]), "+f"(c[1]), "+f"(c[2]), "+f"(c[3])
        : "r"(a[0]), "r"(a[1]), "r"(a[2]), "r"(a[3]), "r"(b0), "r"(b1));
}
__device__ __forceinline__ float sigf(float x) { return 1.f / (1.f + __expf(-x)); }
__device__ __forceinline__ float tanh_fast(float x) {
    return 1.f - 2.f / (__expf(2.f * x) + 1.f);
}
__device__ __forceinline__ void cp16(uint32_t dst, const void* src) {
    asm volatile("cp.async.cg.shared.global [%0], [%1], 16;" :: "r"(dst), "l"(src));
}
#define CP_COMMIT() asm volatile("cp.async.commit_group;" ::: "memory")
#define CP_WAIT0()  asm volatile("cp.async.wait_group 0;" ::: "memory")

// ---------------- merged prep + histogram -----------------------------------
__global__ void k_prep_hist(const float* __restrict__ Wc, const float* __restrict__ Wmix,
                            const float* __restrict__ bmix, const float* __restrict__ bconv,
                            const float* __restrict__ Wih, const float* __restrict__ Whh,
                            const float* __restrict__ bih, const float* __restrict__ bhh,
                            const int* __restrict__ ni, const int* __restrict__ hi,
                            const int* __restrict__ ea) {
    int idx = blockIdx.x * blockDim.x + threadIdx.x;
    if (idx == 0) { g_baseA = 0; g_baseB = 0; }

    if (idx < 8192) {                     // Bef: [2][2 kc][64 c][32] (swizzled)
        int t = idx >> 12, rem = idx & 4095;
        int kc = rem >> 11, rem2 = rem & 2047, c = rem2 >> 5, kk = rem2 & 31;
        int k = kc * 32 + kk;
        float s = 0.f;
        const float* wr = Wc + t * 4096 + k * 64;
        const float* wm = Wmix + (size_t)t * 64 * 64 + c;
#pragma unroll 8
        for (int m = 0; m < 64; m++) s += wr[m] * wm[(size_t)m * 64];
        g_Bef[((t * 2 + kc) * 64 + c) * 32 + swz(kk, c)] = to_tf32(s);
    } else if (idx < 8192 + 36864) {      // Bgru: [4 kc][256 c][36], pair-permuted k
        int i = idx - 8192;
        int kc = i / 9216, rem = i - kc * 9216;
        int c = rem / 36, kkp = rem - c * 36;
        float v = 0.f;
        if (kkp < 32) {
            int k0 = kkp & ~7, r = kkp & 7;
            int kk = k0 + (r >> 1) + ((r & 1) ? 4 : 0);
            int k = kc * 32 + kk;
            int j = c >> 2, seg = c & 3;
            if (k < 64) {
                if (seg == 0)      v = Wih[k * 192 + j];
                else if (seg == 1) v = Wih[k * 192 + 64 + j];
                else if (seg == 2) v = Wih[k * 192 + 128 + j];
            } else {
                int k2 = k - 64;
                if (seg == 0)      v = Whh[k2 * 192 + j];
                else if (seg == 1) v = Whh[k2 * 192 + 64 + j];
                else if (seg == 3) v = Whh[k2 * 192 + 128 + j];
            }
        }
        g_Bgru[i] = to_tf32(v);
    } else if (idx < 45056 + 256) {       // GRU bias (seg-major)
        int c = idx - 45056;
        int seg = c >> 6, j = c & 63;
        float b;
        if (seg == 0)      b = bih[j] + bhh[j];
        else if (seg == 1) b = bih[64 + j] + bhh[64 + j];
        else if (seg == 2) b = bih[128 + j];
        else               b = bhh[128 + j];
        g_bias[c] = b;
    } else if (idx < 45056 + 256 + 64) {  // folded mix bias
        int j = idx - 45056 - 256;
        float s = bmix[j];
        for (int k = 0; k < 128; k++) s += bconv[k] * Wmix[k * 64 + j];
        g_bcmix[j] = s;
    }

    if (idx < NE4) {
        int4 n = ((const int4*)ni)[idx];
        int4 h = ((const int4*)hi)[idx];
        int4 t = ((const int4*)ea)[idx];
        int4 ra, rb;
        ra.x = atomicAdd(&g_cntA[h.x * 2 + t.x], 1);
        ra.y = atomicAdd(&g_cntA[h.y * 2 + t.y], 1);
        ra.z = atomicAdd(&g_cntA[h.z * 2 + t.z], 1);
        ra.w = atomicAdd(&g_cntA[h.w * 2 + t.w], 1);
        rb.x = atomicAdd(&g_cntB[n.x * 2 + t.x], 1);
        rb.y = atomicAdd(&g_cntB[n.y * 2 + t.y], 1);
        rb.z = atomicAdd(&g_cntB[n.z * 2 + t.z], 1);
        rb.w = atomicAdd(&g_cntB[n.w * 2 + t.w], 1);
        ((int4*)g_rankA)[idx] = ra;
        ((int4*)g_rankB)[idx] = rb;
    }
}

// ---------------- zero counters (runs before prep_hist) ---------------------
__global__ void k_zero_cnt() {
    int i = blockIdx.x * 256 + threadIdx.x;
    if (i < NKA) g_cntA[i] = 0;
    if (i < NKB) g_cntB[i] = 0;
}

// ---------------- parallel offsets: block scan + atomic range claim ---------
__global__ __launch_bounds__(1024) void k_offsets() {
    __shared__ int sm[1024];
    __shared__ int blockBase;
    int b = blockIdx.x;
    const int* cnt; int* off; int n; int* gbase;
    if (b < NBA) { cnt = g_cntA; off = g_offA; n = NKA; gbase = &g_baseA; }
    else { b -= NBA; cnt = g_cntB; off = g_offB; n = NKB; gbase = &g_baseB; }
    int tid = threadIdx.x;
    int i = b * 1024 + tid;
    int v = (i < n) ? cnt[i] : 0;
    sm[tid] = v;
    __syncthreads();
    for (int d = 1; d < 1024; d <<= 1) {
        int t = (tid >= d) ? sm[tid - d] : 0;
        __syncthreads();
        sm[tid] += t;
        __syncthreads();
    }
    if (tid == 1023) blockBase = atomicAdd(gbase, sm[1023]);
    __syncthreads();
    if (i < n) off[i] = blockBase + sm[tid] - v;
}

// ---------------- permute: atomic-free scatter, 4 edges/thread --------------
__global__ void k_perm(const int* __restrict__ ni, const int* __restrict__ hi,
                       const int* __restrict__ ea) {
    int i = blockIdx.x * 256 + threadIdx.x;
    if (i >= NE4) return;
    int4 n = ((const int4*)ni)[i];
    int4 h = ((const int4*)hi)[i];
    int4 t = ((const int4*)ea)[i];
    int4 ra = ((const int4*)g_rankA)[i];
    int4 rb = ((const int4*)g_rankB)[i];
    g_sortA[g_offA[h.x * 2 + t.x] + ra.x] = n.x;
    g_sortA[g_offA[h.y * 2 + t.y] + ra.y] = n.y;
    g_sortA[g_offA[h.z * 2 + t.z] + ra.z] = n.z;
    g_sortA[g_offA[h.w * 2 + t.w] + ra.w] = n.w;
    g_sortB[g_offB[n.x * 2 + t.x] + rb.x] = (t.x * NH + h.x) * 64;
    g_sortB[g_offB[n.y * 2 + t.y] + rb.y] = (t.y * NH + h.y) * 64;
    g_sortB[g_offB[n.z * 2 + t.z] + rb.z] = (t.z * NH + h.z) * 64;
    g_sortB[g_offB[n.w * 2 + t.w] + rb.w] = (t.w * NH + h.w) * 64;
}

// ---------------- gather A: half-warp per row, float4 lanes -----------------
__global__ __launch_bounds__(256) void k_gatherA(const float* __restrict__ x) {
    cudaTriggerProgrammaticLaunchCompletion();   // let k_mma_ef prologue start
    int key = (blockIdx.x * 256 + threadIdx.x) >> 5;
    if (key >= NKA) return;
    int lane = threadIdx.x & 31;
    int half = lane >> 4, sub = lane & 15;
    int t = key & 1, h = key >> 1;
    int base = g_offA[key], cnt = g_cntA[key];
    const float* xb = x + sub * 4;
    float4 acc = make_float4(0.f, 0.f, 0.f, 0.f);
    int i = 0;
    for (; i + 4 <= cnt; i += 4) {
        int n0 = g_sortA[base + i + half];
        int n1 = g_sortA[base + i + 2 + half];
        float4 v0 = *(const float4*)(xb + (size_t)n0 * 64);
        float4 v1 = *(const float4*)(xb + (size_t)n1 * 64);
        acc.x += v0.x + v1.x; acc.y += v0.y + v1.y;
        acc.z += v0.z + v1.z; acc.w += v0.w + v1.w;
    }
    for (; i < cnt; i += 2) {
        int idx = i + half;
        if (idx < cnt) {
            int n = g_sortA[base + idx];
            float4 v = *(const float4*)(xb + (size_t)n * 64);
            acc.x += v.x; acc.y += v.y; acc.z += v.z; acc.w += v.w;
        }
    }
    acc.x += __shfl_xor_sync(0xffffffffu, acc.x, 16);
    acc.y += __shfl_xor_sync(0xffffffffu, acc.y, 16);
    acc.z += __shfl_xor_sync(0xffffffffu, acc.z, 16);
    acc.w += __shfl_xor_sync(0xffffffffu, acc.w, 16);
    if (half == 0) {
        float s = (cnt > 0) ? 1.f / (float)cnt : 0.f;
        acc.x *= s; acc.y *= s; acc.z *= s; acc.w *= s;
        *(float4*)&g_aggA[((size_t)t * NH + h) * 64 + sub * 4] = acc;
    }
}

// ---------------- GEMM: efm = aggA @ Wcomb_t (fp16 out), PDL secondary ------
__global__ __launch_bounds__(256) void k_mma_ef() {
    __shared__ __align__(16) float As[128][32];
    __shared__ __align__(16) float Bs[2][64][32];
    int tid = threadIdx.x;
    int lane = tid & 31, warp = tid >> 5;
    int warpM = warp >> 1, warpN = warp & 1;
    int g = lane >> 2, t4 = lane & 3;
    int rot = (g & 3) << 3;
    int n0 = blockIdx.x * 128;
    int ty = blockIdx.y;

    // prologue (independent of gatherA): load both B chunks
    {
        const float4* src = (const float4*)&g_Bef[ty * 4096];
        float4* dst = (float4*)&Bs[0][0][0];
        for (int i = tid; i < 1024; i += 256) dst[i] = src[i];
    }
    cudaGridDependencySynchronize();   // wait for gatherA's aggA

    float acc[2][4][4] = {};
    for (int kc = 0; kc < 2; kc++) {
        __syncthreads();
        for (int i = tid; i < 4096; i += 256) {
            int m = i >> 5, kk = i & 31;
            int n = n0 + m;
            float v = (n < NH) ? g_aggA[((size_t)ty * NH + n) * 64 + kc * 32 + kk] : 0.f;
            As[m][swz(kk, m)] = to_tf32(v);
        }
        __syncthreads();
#pragma unroll
        for (int s = 0; s < 4; s++) {
            int pc = (s * 8 + 2 * t4 + rot) & 31;
            uint32_t a[2][4];
#pragma unroll
            for (int mt = 0; mt < 2; mt++) {
                int r = warpM * 32 + mt * 16 + g;
                float2 lo = *(const float2*)&As[r][pc];
                float2 hi = *(const float2*)&As[r + 8][pc];
                a[mt][0] = __float_as_uint(lo.x); a[mt][1] = __float_as_uint(hi.x);
                a[mt][2] = __float_as_uint(lo.y); a[mt][3] = __float_as_uint(hi.y);
            }
#pragma unroll
            for (int nt = 0; nt < 4; nt++) {
                int c = warpN * 32 + nt * 8 + g;
                float2 b = *(const float2*)&Bs[kc][c][pc];
                uint32_t b0 = __float_as_uint(b.x), b1 = __float_as_uint(b.y);
                mma_tf32(acc[0][nt], a[0], b0, b1);
                mma_tf32(acc[1][nt], a[1], b0, b1);
            }
        }
    }
#pragma unroll
    for (int mt = 0; mt < 2; mt++) {
        int r = n0 + warpM * 32 + mt * 16 + g;
#pragma unroll
        for (int nt = 0; nt < 4; nt++) {
            int c = warpN * 32 + nt * 8 + 2 * t4;
            if (r < NH)
                *(__half2*)&g_efmh[((size_t)ty * NH + r) * 64 + c] =
                    __floats2half2_rn(acc[mt][nt][0], acc[mt][nt][1]);
            if (r + 8 < NH)
                *(__half2*)&g_efmh[((size_t)ty * NH + r + 8) * 64 + c] =
                    __floats2half2_rn(acc[mt][nt][2], acc[mt][nt][3]);
        }
    }
}

// ---------------- gather B: fp16 rows, half-warp per row --------------------
__global__ __launch_bounds__(256) void k_gatherB() {
    cudaTriggerProgrammaticLaunchCompletion();   // let k_gru prologue start
    int node = (blockIdx.x * 256 + threadIdx.x) >> 5;
    if (node >= NN) return;
    int lane = threadIdx.x & 31;
    int half = lane >> 4, sub = lane & 15;
    const __half* eb = g_efmh + sub * 4;
    float4 tot = make_float4(0.f, 0.f, 0.f, 0.f);
#pragma unroll
    for (int t = 0; t < 2; t++) {
        int key = node * 2 + t;
        int base = g_offB[key], cnt = g_cntB[key];
        float4 acc = make_float4(0.f, 0.f, 0.f, 0.f);
        int i = 0;
        for (; i + 4 <= cnt; i += 4) {
            int o0 = g_sortB[base + i + half];
            int o1 = g_sortB[base + i + 2 + half];
            uint2 r0 = *(const uint2*)(eb + o0);
            uint2 r1 = *(const uint2*)(eb + o1);
            float2 f0 = __half22float2(*reinterpret_cast<__half2*>(&r0.x));
            float2 f1 = __half22float2(*reinterpret_cast<__half2*>(&r0.y));
            float2 f2 = __half22float2(*reinterpret_cast<__half2*>(&r1.x));
            float2 f3 = __half22float2(*reinterpret_cast<__half2*>(&r1.y));
            acc.x += f0.x + f2.x; acc.y += f0.y + f2.y;
            acc.z += f1.x + f3.x; acc.w += f1.y + f3.y;
        }
        for (; i < cnt; i += 2) {
            int idx = i + half;
            if (idx < cnt) {
                int o = g_sortB[base + idx];
                uint2 r0 = *(const uint2*)(eb + o);
                float2 f0 = __half22float2(*reinterpret_cast<__half2*>(&r0.x));
                float2 f1 = __half22float2(*reinterpret_cast<__half2*>(&r0.y));
                acc.x += f0.x; acc.y += f0.y; acc.z += f1.x; acc.w += f1.y;
            }
        }
        float s = (cnt > 0) ? 1.f / (float)cnt : 0.f;
        tot.x += acc.x * s; tot.y += acc.y * s;
        tot.z += acc.z * s; tot.w += acc.w * s;
    }
    tot.x += __shfl_xor_sync(0xffffffffu, tot.x, 16);
    tot.y += __shfl_xor_sync(0xffffffffu, tot.y, 16);
    tot.z += __shfl_xor_sync(0xffffffffu, tot.z, 16);
    tot.w += __shfl_xor_sync(0xffffffffu, tot.w, 16);
    if (half == 0) {
        float4 b = *(const float4*)&g_bcmix[sub * 4];
        float4 o;
        o.x = fmaxf(tot.x + b.x, 0.f); o.y = fmaxf(tot.y + b.y, 0.f);
        o.z = fmaxf(tot.z + b.z, 0.f); o.w = fmaxf(tot.w + b.w, 0.f);
        *(float4*)&g_h[(size_t)node * 64 + sub * 4] = o;
    }
}

// ---------------- persistent GRU: B-resident, PDL secondary -----------------
// smem floats: Ball[4][256][36]=36864 | As[2][128][36]=9216 | Wro3 256 | sred 512
//              | Hs[128][68]=8704  (h_next output staging)
#define OF_AS   36864
#define OF_WRO  46080
#define OF_SRED 46336
#define OF_HS   46848
#define GRU_SMEM ((46848 + 8704) * 4)
__global__ __launch_bounds__(512) void k_gru(const float* __restrict__ h_prev,
                                             const float* __restrict__ Wro,
                                             const float* __restrict__ bro,
                                             float* __restrict__ out_h,
                                             float* __restrict__ out3) {
    extern __shared__ __align__(16) float sm[];
    uint32_t smb;
    asm("{ .reg .u64 t; cvta.to.shared.u64 t, %1; cvt.u32.u64 %0, t; }"
        : "=r"(smb) : "l"(sm));
    int tid = threadIdx.x;
    int lane = tid & 31, warp = tid >> 5;
    int warpM = warp >> 2, warpN = warp & 3;
    int g = lane >> 2, t = lane & 3;

    // ---- prologue (independent of gatherB): B load + constants ----
    for (int i = tid; i < 9216; i += 512)
        cp16(smb + (uint32_t)i * 16, (const char*)g_Bgru + (size_t)i * 16);
    CP_COMMIT();
    if (tid < 256) {
        int j = tid >> 2, c = tid & 3;
        sm[OF_WRO + tid] = (c < 3) ? __ldg(&Wro[j * 64 + c]) : 0.f;
    }
    sm[OF_SRED + tid] = 0.f;
    float brd0 = __ldg(&bro[0]), brd1 = __ldg(&bro[1]), brd2 = __ldg(&bro[2]);

    cudaGridDependencySynchronize();   // wait for gatherB's g_h

#define STAGE_A(ptile, pkc) do {                                               \
        int _kc = (pkc);                                                       \
        uint32_t _dst = smb + (OF_AS + (_kc & 1) * 4608) * 4;                  \
        for (int i = tid; i < 1024; i += 512) {                                \
            int m = i >> 3, q = i & 7;                                         \
            int n = (ptile) * 128 + m;                                         \
            int nc = (n < NN) ? n : (NN - 1);                                  \
            const float* src = (_kc < 2)                                       \
                ? &g_h[(size_t)nc * 64 + _kc * 32 + q * 4]                     \
                : &h_prev[(size_t)nc * 64 + (_kc - 2) * 32 + q * 4];           \
            cp16(_dst + (uint32_t)(m * 144 + q * 16), src);                    \
        }                                                                      \
    } while (0)

    int tile = blockIdx.x;
    if (tile < NT) STAGE_A(tile, 0);
    CP_COMMIT();

    for (; tile < NT; tile += GRID_GRU) {
        int n0 = tile * 128;
        float acc[2][8][4] = {};
        for (int kc = 0; kc < 4; kc++) {
            CP_WAIT0();
            __syncthreads();
            if (kc < 3) { STAGE_A(tile, kc + 1); CP_COMMIT(); }
            const float* As = sm + OF_AS + (kc & 1) * 4608;
            const float* Bb = sm + kc * 9216;
#pragma unroll
            for (int s = 0; s < 4; s++) {
                int k0 = s * 8;
                uint32_t a[2][4];
#pragma unroll
                for (int mt = 0; mt < 2; mt++) {
                    int r = warpM * 32 + mt * 16 + g;
                    a[mt][0] = __float_as_uint(As[r * 36 + k0 + t]);
                    a[mt][1] = __float_as_uint(As[(r + 8) * 36 + k0 + t]);
                    a[mt][2] = __float_as_uint(As[r * 36 + k0 + t + 4]);
                    a[mt][3] = __float_as_uint(As[(r + 8) * 36 + k0 + t + 4]);
                }
#pragma unroll
                for (int nt = 0; nt < 8; nt++) {
                    int c = warpN * 64 + nt * 8 + g;
                    float2 bb = *(const float2*)&Bb[c * 36 + k0 + 2 * t];
                    mma_tf32(acc[0][nt], a[0],
                             __float_as_uint(bb.x), __float_as_uint(bb.y));
                    mma_tf32(acc[1][nt], a[1],
                             __float_as_uint(bb.x), __float_as_uint(bb.y));
                }
            }
        }

        // ---- gate epilogue: hp from As bufs (h_prev resident), hn -> Hs ----
        const float* Ab0 = sm + OF_AS;
        const float* Ab1 = sm + OF_AS + 4608;
        float p[2][2][3] = {};
        bool even = (t & 1) == 0;
#pragma unroll
        for (int mt = 0; mt < 2; mt++) {
#pragma unroll
            for (int nt = 0; nt < 8; nt++) {
                int j = warpN * 16 + nt * 2 + (t >> 1);
                float br = g_bias[j], bz = g_bias[64 + j];
                float bn = g_bias[128 + j], bh = g_bias[192 + j];
                float w0 = sm[OF_WRO + j * 4 + 0];
                float w1 = sm[OF_WRO + j * 4 + 1];
                float w2 = sm[OF_WRO + j * 4 + 2];
#pragma unroll
                for (int rh = 0; rh < 2; rh++) {
                    int m = warpM * 32 + mt * 16 + rh * 8 + g;
                    float v0 = acc[mt][nt][rh * 2 + 0];
                    float v1 = acc[mt][nt][rh * 2 + 1];
                    float o0 = __shfl_xor_sync(0xffffffffu, v0, 1);
                    float o1 = __shfl_xor_sync(0xffffffffu, v1, 1);
                    float hn = 0.f;
                    if (even) {
                        float r_ = sigf(v0 + br);
                        float z_ = sigf(v1 + bz);
                        float nv = tanh_fast((o0 + bn) + r_ * (o1 + bh));
                        float hp = (j < 32) ? Ab0[m * 36 + j] : Ab1[m * 36 + j - 32];
                        hn = (1.f - z_) * nv + z_ * hp;
                        sm[OF_HS + m * 68 + j] = hn;
                    }
                    p[mt][rh][0] += hn * w0;
                    p[mt][rh][1] += hn * w1;
                    p[mt][rh][2] += hn * w2;
                }
            }
        }
#pragma unroll
        for (int mt = 0; mt < 2; mt++)
#pragma unroll
            for (int rh = 0; rh < 2; rh++)
#pragma unroll
                for (int c = 0; c < 3; c++) {
                    float v = p[mt][rh][c] + __shfl_xor_sync(0xffffffffu, p[mt][rh][c], 2);
                    if (t == 0)
                        atomicAdd(&sm[OF_SRED + (warpM * 32 + mt * 16 + rh * 8 + g) * 4 + c], v);
                }
        __syncthreads();

        // prefetch next tile's first A chunk (overlaps the stores below)
        {
            int pt = tile + GRID_GRU;
            if (pt < NT) { STAGE_A(pt, 0); CP_COMMIT(); }
        }

        // ---- coalesced Hs -> out_h, plus out3 ----
        for (int i = tid; i < 2048; i += 512) {
            int m = i >> 4, q = i & 15;
            int n = n0 + m;
            if (n < NN)
                *(float4*)&out_h[(size_t)n * 64 + q * 4] =
                    *(const float4*)&sm[OF_HS + m * 68 + q * 4];
        }
        {
            int nd = tid >> 2, c = tid & 3;
            int n = n0 + nd;
            if (c < 3 && n < NN)
                out3[(size_t)n * 3 + c] = sm[OF_SRED + tid] +
                                          (c == 0 ? brd0 : (c == 1 ? brd1 : brd2));
        }
        __syncthreads();
        sm[OF_SRED + tid] = 0.f;
    }
#undef STAGE_A
}

// ---------------- launch -----------------------------------------------------
extern "C" void kernel_launch(void* const* d_in, const int* in_sizes, int n_in,
                              void* d_out, int out_size) {
    const float* x       = (const float*)d_in[0];
    const float* h_prev  = (const float*)d_in[1];
    const int* node_idx  = (const int*)d_in[2];
    const int* hedge_idx = (const int*)d_in[3];
    const int* edge_attr = (const int*)d_in[4];
    const float* W_conv  = (const float*)d_in[5];
    const float* b_conv  = (const float*)d_in[6];
    const float* W_mix   = (const float*)d_in[7];
    const float* b_mix   = (const float*)d_in[8];
    const float* W_ih    = (const float*)d_in[9];
    const float* W_hh    = (const float*)d_in[10];
    const float* b_ih    = (const float*)d_in[11];
    const float* b_hh    = (const float*)d_in[12];
    const float* W_ro    = (const float*)d_in[13];
    const float* b_ro    = (const float*)d_in[14];

    float* h_next = (float*)d_out;
    float* out3   = (float*)d_out + (size_t)NN * 64;

    cudaFuncSetAttribute(k_gru, cudaFuncAttributeMaxDynamicSharedMemorySize, GRU_SMEM);

    k_zero_cnt<<<(NKB + 255) / 256, 256>>>();
    k_prep_hist<<<(NE4 + 255) / 256, 256>>>(W_conv, W_mix, b_mix, b_conv,
                                            W_ih, W_hh, b_ih, b_hh,
                                            node_idx, hedge_idx, edge_attr);
    k_offsets<<<NBA + NBB, 1024>>>();
    k_perm<<<(NE4 + 255) / 256, 256>>>(node_idx, hedge_idx, edge_attr);
    k_gatherA<<<(NKA * 32 + 255) / 256, 256>>>(x);

    // PDL secondaries: prologue (B loads) overlaps the triggering primary
    cudaLaunchAttribute pdl[1];
    pdl[0].id = cudaLaunchAttributeProgrammaticStreamSerialization;
    pdl[0].val.programmaticStreamSerializationAllowed = 1;

    {
        cudaLaunchConfig_t cfg = {};
        cfg.gridDim = dim3((NH + 127) / 128, 2);
        cfg.blockDim = dim3(256);
        cfg.attrs = pdl; cfg.numAttrs = 1;
        cudaLaunchKernelEx(&cfg, k_mma_ef);
    }
    k_gatherB<<<(NN * 32 + 255) / 256, 256>>>();
    {
        cudaLaunchConfig_t cfg = {};
        cfg.gridDim = dim3(GRID_GRU);
        cfg.blockDim = dim3(512);
        cfg.dynamicSmemBytes = GRU_SMEM;
        cfg.attrs = pdl; cfg.numAttrs = 1;
        cudaLaunchKernelEx(&cfg, k_gru, h_prev, W_ro, b_ro, h_next, out3);
    }
}